// round 7
// baseline (speedup 1.0000x reference)
#include <cuda_runtime.h>
#include <math.h>
#include <stdint.h>

// ---------------- problem constants ----------------
#define CC     10
#define NCLUST 11            // C+1
#define NSEG   88            // B * (C+1)
#define BATCH  8
#define NPB    16384         // tokens per batch
#define MTOT   131072        // B*N
#define IDIM   512
#define EMBD   8
#define DDIM   256

// ---------------- scratch (static device globals) ----------------
__device__ float g_x[(size_t)MTOT * IDIM];     // fused features (stored tf32-rounded), 256 MiB
__device__ float g_A[MTOT];                    // intra attention logits (bc1 folded out: softmax-invariant)
__device__ float g_ex[MTOT];                   // exp(A - segmax)
__device__ float g_segmax[NSEG];
__device__ float g_segsum[NSEG];
__device__ int   g_counts[NSEG];
__device__ float g_cfraw[NSEG * IDIM];
__device__ float g_cfeat[NSEG * IDIM];
__device__ float g_A2[NSEG];
// tf32-rounded weight copies (unbiased mma operands at zero inner-loop cost)
__device__ float g_rWf[IDIM * IDIM];           // W_fuse rows 0..511
__device__ float g_rWa1[IDIM * DDIM];
__device__ float g_rWb1[IDIM * DDIM];

// ---------------- helpers ----------------
__device__ __forceinline__ void atomicMaxFloat(float* addr, float val) {
    int* ia = (int*)addr;
    int old = *ia;
    while (__int_as_float(old) < val) {
        int assumed = old;
        old = atomicCAS(ia, assumed, __float_as_int(val));
        if (old == assumed) break;
    }
}

__device__ __forceinline__ float sigmoidf_(float v) {
    return 1.0f / (1.0f + expf(-v));
}

__device__ __forceinline__ uint32_t f2tf32(float x) {  // round-to-nearest tf32, result as f32 bits
    uint32_t r;
    asm("cvt.rna.tf32.f32 %0, %1;" : "=r"(r) : "f"(x));
    return r;
}
__device__ __forceinline__ float roundtf(float x) { return __uint_as_float(f2tf32(x)); }

__device__ __forceinline__ uint32_t smem_u32(const void* p) {
    return (uint32_t)__cvta_generic_to_shared(p);
}
__device__ __forceinline__ void cp16(uint32_t dst, const void* src) {
    asm volatile("cp.async.cg.shared.global [%0], [%1], 16;" :: "r"(dst), "l"(src));
}
#define CP_COMMIT()  asm volatile("cp.async.commit_group;")
#define CP_WAIT2()   asm volatile("cp.async.wait_group 2;")
#define CP_WAIT1()   asm volatile("cp.async.wait_group 1;")
#define CP_WAIT0()   asm volatile("cp.async.wait_group 0;")

// m16n8k8 tf32 mma, row.col, fp32 accum. All operands are pre-rounded (rna) -> unbiased.
__device__ __forceinline__ void mma_tf32(float* d, const uint32_t* a, const uint32_t* b) {
    asm volatile(
        "mma.sync.aligned.m16n8k8.row.col.f32.tf32.tf32.f32 "
        "{%0,%1,%2,%3}, {%4,%5,%6,%7}, {%8,%9}, {%0,%1,%2,%3};\n"
        : "+f"(d[0]), "+f"(d[1]), "+f"(d[2]), "+f"(d[3])
        : "r"(a[0]), "r"(a[1]), "r"(a[2]), "r"(a[3]), "r"(b[0]), "r"(b[1]));
}

// ---------------- kernel 0: init + weight rounding prepass ----------------
__global__ void init_kernel(const float* __restrict__ Wf,
                            const float* __restrict__ Wa1,
                            const float* __restrict__ Wb1) {
    int gtid = blockIdx.x * blockDim.x + threadIdx.x;
    int stride = gridDim.x * blockDim.x;
    for (int i = gtid; i < MTOT; i += stride) g_A[i] = 0.0f;
    for (int i = gtid; i < NSEG * IDIM; i += stride) g_cfraw[i] = 0.0f;
    for (int i = gtid; i < IDIM * IDIM; i += stride) g_rWf[i] = roundtf(Wf[i]);
    for (int i = gtid; i < IDIM * DDIM; i += stride) {
        g_rWa1[i] = roundtf(Wa1[i]);
        g_rWb1[i] = roundtf(Wb1[i]);
    }
    if (gtid < NSEG) {
        g_segmax[gtid] = -1e30f;
        g_segsum[gtid] = 0.0f;
        g_counts[gtid] = 0;
    }
}

// ---------------- kernel 1: x = relu([h | emb[cid]] @ W_fuse + b_fuse) ----------------
// tf32 mma, block 128(M) x 128(N), 8 warps 4x2 -> warp 32x64, BK=32, 3-stage cp.async ring.
// h is rounded in-smem after landing; Wf comes pre-rounded; output stored tf32-rounded.
#define F_AS_STRIDE 36
#define F_BS_STRIDE 136
#define F_AS_ELEMS  (128 * F_AS_STRIDE)
#define F_BS_ELEMS  (32 * F_BS_STRIDE)
#define F_DSMEM_BYTES ((3 * F_AS_ELEMS + 3 * F_BS_ELEMS) * 4)

__global__ __launch_bounds__(256) void fuse_mma_kernel(
    const float* __restrict__ h, const int* __restrict__ cids,
    const float* __restrict__ emb, const float* __restrict__ Wf,
    const float* __restrict__ bf)
{
    extern __shared__ float dsm[];
    float* Asb = dsm;                       // [3][128][36]
    float* Bsb = dsm + 3 * F_AS_ELEMS;      // [3][32][136]
    __shared__ float sWe[8][128];
    __shared__ float sbf[128];
    __shared__ float semb[NCLUST * EMBD];
    __shared__ int   scids[128];

    const int tid  = threadIdx.x;
    const int m0   = blockIdx.y * 128;
    const int n0   = blockIdx.x * 128;
    const int warp = tid >> 5, lane = tid & 31;
    const int gid  = lane >> 2, tig = lane & 3;
    const int wm   = (warp >> 1) * 32, wn = (warp & 1) * 64;

    if (tid < 128) { int c = cids[m0 + tid]; scids[tid] = min(max(c, 0), CC); }
    if (tid < 128) sbf[tid] = bf[n0 + tid];
    if (tid < NCLUST * EMBD) semb[tid] = emb[tid];
    for (int t = tid; t < 8 * 128; t += 256) {
        int e = t >> 7, n = t & 127;
        sWe[e][n] = Wf[(size_t)(IDIM + e) * IDIM + n0 + n];
    }

    float acc[2][8][4];
#pragma unroll
    for (int mi = 0; mi < 2; mi++)
#pragma unroll
        for (int ni = 0; ni < 8; ni++)
#pragma unroll
            for (int c = 0; c < 4; c++) acc[mi][ni][c] = 0.0f;

    auto load_slab = [&](int kt, int st) {
        const int k0 = kt * 32;
        float* a = Asb + st * F_AS_ELEMS;
        float* b = Bsb + st * F_BS_ELEMS;
#pragma unroll
        for (int i = 0; i < 4; i++) {
            int idx = i * 256 + tid;
            int row = idx >> 3, c4 = (idx & 7) * 4;
            cp16(smem_u32(a + row * F_AS_STRIDE + c4),
                 h + (size_t)(m0 + row) * IDIM + k0 + c4);
        }
#pragma unroll
        for (int i = 0; i < 4; i++) {
            int idx = i * 256 + tid;
            int kk = idx >> 5, c4 = (idx & 31) * 4;
            cp16(smem_u32(b + kk * F_BS_STRIDE + c4),
                 g_rWf + (size_t)(k0 + kk) * IDIM + n0 + c4);
        }
    };

    load_slab(0, 0); CP_COMMIT();
    load_slab(1, 1); CP_COMMIT();

    for (int kt = 0; kt < 16; kt++) {
        const int cur = kt % 3;
        if (kt < 14)      { load_slab(kt + 2, (kt + 2) % 3); CP_COMMIT(); CP_WAIT2(); }
        else if (kt == 14){ CP_WAIT1(); }
        else              { CP_WAIT0(); }
        __syncthreads();

        // round A slab in place (rna) before mma consumption; thread t owns row t>>1, 16 cols
        {
            float* a = Asb + cur * F_AS_ELEMS;
            float* p = a + (tid >> 1) * F_AS_STRIDE + (tid & 1) * 16;
#pragma unroll
            for (int q = 0; q < 4; q++) {
                float4 v = *(float4*)(p + q * 4);
                v.x = roundtf(v.x); v.y = roundtf(v.y);
                v.z = roundtf(v.z); v.w = roundtf(v.w);
                *(float4*)(p + q * 4) = v;
            }
        }
        __syncthreads();

        const uint32_t* a = (const uint32_t*)(Asb + cur * F_AS_ELEMS);
        const uint32_t* b = (const uint32_t*)(Bsb + cur * F_BS_ELEMS);
#pragma unroll
        for (int ks = 0; ks < 4; ks++) {
            const int kb = ks * 8;
            uint32_t af[2][4], bfr[8][2];
#pragma unroll
            for (int mi = 0; mi < 2; mi++) {
                int mr = wm + mi * 16 + gid;
                af[mi][0] = a[mr * F_AS_STRIDE + kb + tig];
                af[mi][1] = a[(mr + 8) * F_AS_STRIDE + kb + tig];
                af[mi][2] = a[mr * F_AS_STRIDE + kb + tig + 4];
                af[mi][3] = a[(mr + 8) * F_AS_STRIDE + kb + tig + 4];
            }
#pragma unroll
            for (int ni = 0; ni < 8; ni++) {
                int nc = wn + ni * 8 + gid;
                bfr[ni][0] = b[(kb + tig) * F_BS_STRIDE + nc];
                bfr[ni][1] = b[(kb + tig + 4) * F_BS_STRIDE + nc];
            }
#pragma unroll
            for (int mi = 0; mi < 2; mi++)
#pragma unroll
                for (int ni = 0; ni < 8; ni++)
                    mma_tf32(acc[mi][ni], af[mi], bfr[ni]);
        }
        __syncthreads();
    }

    // epilogue: emb contribution + bias + relu; store tf32-rounded (unbiased operand for attn1)
#pragma unroll
    for (int mi = 0; mi < 2; mi++) {
#pragma unroll
        for (int half = 0; half < 2; half++) {
            int ml = wm + mi * 16 + gid + half * 8;
            int m  = m0 + ml;
            const float* ev = &semb[scids[ml] * EMBD];
#pragma unroll
            for (int ni = 0; ni < 8; ni++) {
                int nl = wn + ni * 8 + 2 * tig;
                float e0 = 0.0f, e1 = 0.0f;
#pragma unroll
                for (int e = 0; e < 8; e++) {
                    e0 += ev[e] * sWe[e][nl];
                    e1 += ev[e] * sWe[e][nl + 1];
                }
                float o0 = fmaxf(acc[mi][ni][half * 2 + 0] + e0 + sbf[nl],     0.0f);
                float o1 = fmaxf(acc[mi][ni][half * 2 + 1] + e1 + sbf[nl + 1], 0.0f);
                *(float2*)&g_x[(size_t)m * IDIM + n0 + nl] =
                    make_float2(roundtf(o0), roundtf(o1));
            }
        }
    }
}

// ---------------- kernel 2: intra gated attention logits (dual tf32 mma, 3-stage pipeline) ----------------
// block 128(M) x 64(D), 8 warps 4x2 -> warp 32x32. A (g_x) and B (g_rW*) are pre-rounded.
#define A_AS_STRIDE 36
#define A_BS_STRIDE 72
#define A_AS_ELEMS  (128 * A_AS_STRIDE)
#define A_BS_ELEMS  (32 * A_BS_STRIDE)
#define A_DSMEM_BYTES ((3 * A_AS_ELEMS + 6 * A_BS_ELEMS) * 4)

__global__ __launch_bounds__(256) void attn1_mma_kernel(
    const float* __restrict__ ba1, const float* __restrict__ bb1,
    const float* __restrict__ Wc1)
{
    extern __shared__ float dsm[];
    float* Asb = dsm;                                  // [3][128][36]
    float* Bab = dsm + 3 * A_AS_ELEMS;                 // [3][32][72]
    float* Bbb = dsm + 3 * A_AS_ELEMS + 3 * A_BS_ELEMS;// [3][32][72]
    __shared__ float sba[64], sbb[64], swc[64];
    __shared__ float sA[128];

    const int tid  = threadIdx.x;
    const int m0   = blockIdx.y * 128;
    const int d0   = blockIdx.x * 64;
    const int warp = tid >> 5, lane = tid & 31;
    const int gid  = lane >> 2, tig = lane & 3;
    const int wm   = (warp >> 1) * 32, wn = (warp & 1) * 32;

    if (tid < 64) { sba[tid] = ba1[d0 + tid]; sbb[tid] = bb1[d0 + tid]; swc[tid] = Wc1[d0 + tid]; }
    if (tid < 128) sA[tid] = 0.0f;

    float acca[2][4][4], accg[2][4][4];
#pragma unroll
    for (int mi = 0; mi < 2; mi++)
#pragma unroll
        for (int ni = 0; ni < 4; ni++)
#pragma unroll
            for (int c = 0; c < 4; c++) { acca[mi][ni][c] = 0.0f; accg[mi][ni][c] = 0.0f; }

    auto load_slab = [&](int kt, int st) {
        const int k0 = kt * 32;
        float* a  = Asb + st * A_AS_ELEMS;
        float* ba = Bab + st * A_BS_ELEMS;
        float* bb = Bbb + st * A_BS_ELEMS;
#pragma unroll
        for (int i = 0; i < 4; i++) {
            int idx = i * 256 + tid;
            int row = idx >> 3, c4 = (idx & 7) * 4;
            cp16(smem_u32(a + row * A_AS_STRIDE + c4),
                 g_x + (size_t)(m0 + row) * IDIM + k0 + c4);
        }
#pragma unroll
        for (int i = 0; i < 2; i++) {
            int idx = i * 256 + tid;
            int kk = idx >> 4, c4 = (idx & 15) * 4;
            cp16(smem_u32(ba + kk * A_BS_STRIDE + c4),
                 g_rWa1 + (size_t)(k0 + kk) * DDIM + d0 + c4);
            cp16(smem_u32(bb + kk * A_BS_STRIDE + c4),
                 g_rWb1 + (size_t)(k0 + kk) * DDIM + d0 + c4);
        }
    };

    load_slab(0, 0); CP_COMMIT();
    load_slab(1, 1); CP_COMMIT();

    for (int kt = 0; kt < 16; kt++) {
        const int cur = kt % 3;
        if (kt < 14)      { load_slab(kt + 2, (kt + 2) % 3); CP_COMMIT(); CP_WAIT2(); }
        else if (kt == 14){ CP_WAIT1(); }
        else              { CP_WAIT0(); }
        __syncthreads();
        const uint32_t* a  = (const uint32_t*)(Asb + cur * A_AS_ELEMS);
        const uint32_t* ba = (const uint32_t*)(Bab + cur * A_BS_ELEMS);
        const uint32_t* bb = (const uint32_t*)(Bbb + cur * A_BS_ELEMS);
#pragma unroll
        for (int ks = 0; ks < 4; ks++) {
            const int kb = ks * 8;
            uint32_t af[2][4];
#pragma unroll
            for (int mi = 0; mi < 2; mi++) {
                int mr = wm + mi * 16 + gid;
                af[mi][0] = a[mr * A_AS_STRIDE + kb + tig];
                af[mi][1] = a[(mr + 8) * A_AS_STRIDE + kb + tig];
                af[mi][2] = a[mr * A_AS_STRIDE + kb + tig + 4];
                af[mi][3] = a[(mr + 8) * A_AS_STRIDE + kb + tig + 4];
            }
#pragma unroll
            for (int ni = 0; ni < 4; ni++) {
                int nc = wn + ni * 8 + gid;
                uint32_t ba_[2], bb_[2];
                ba_[0] = ba[(kb + tig) * A_BS_STRIDE + nc];
                ba_[1] = ba[(kb + tig + 4) * A_BS_STRIDE + nc];
                bb_[0] = bb[(kb + tig) * A_BS_STRIDE + nc];
                bb_[1] = bb[(kb + tig + 4) * A_BS_STRIDE + nc];
#pragma unroll
                for (int mi = 0; mi < 2; mi++) {
                    mma_tf32(acca[mi][ni], af[mi], ba_);
                    mma_tf32(accg[mi][ni], af[mi], bb_);
                }
            }
        }
        __syncthreads();
    }

    // epilogue: gated pointwise + row reduction over this 64-d slab
    float rsum[2][2];
    rsum[0][0] = rsum[0][1] = rsum[1][0] = rsum[1][1] = 0.0f;
#pragma unroll
    for (int mi = 0; mi < 2; mi++)
#pragma unroll
        for (int ni = 0; ni < 4; ni++) {
            int nl = wn + ni * 8 + 2 * tig;
#pragma unroll
            for (int half = 0; half < 2; half++) {
#pragma unroll
                for (int col = 0; col < 2; col++) {
                    int dl = nl + col;
                    float va = tanhf(acca[mi][ni][half * 2 + col] + sba[dl]);
                    float vg = sigmoidf_(accg[mi][ni][half * 2 + col] + sbb[dl]);
                    rsum[mi][half] += va * vg * swc[dl];
                }
            }
        }
#pragma unroll
    for (int mi = 0; mi < 2; mi++)
#pragma unroll
        for (int half = 0; half < 2; half++) {
            float v = rsum[mi][half];
            v += __shfl_xor_sync(0xffffffffu, v, 1);
            v += __shfl_xor_sync(0xffffffffu, v, 2);
            if (tig == 0) atomicAdd(&sA[wm + mi * 16 + gid + half * 8], v);
        }
    __syncthreads();
    if (tid < 128) atomicAdd(&g_A[m0 + tid], sA[tid]);
}

// ---------------- kernel 3: segment max ----------------
__global__ void segmax_kernel(const int* __restrict__ cids) {
    __shared__ float smax[NSEG];
    const int tid = threadIdx.x;
    if (tid < NSEG) smax[tid] = -1e30f;
    __syncthreads();
    for (int m = blockIdx.x * blockDim.x + tid; m < MTOT; m += gridDim.x * blockDim.x) {
        int cid = cids[m];
        cid = min(max(cid, 0), CC);
        int seg = (m >> 14) * NCLUST + cid;
        atomicMaxFloat(&smax[seg], g_A[m]);
    }
    __syncthreads();
    if (tid < NSEG) atomicMaxFloat(&g_segmax[tid], smax[tid]);
}

// ---------------- kernel 4: ex = exp(A - segmax), segment sum + counts ----------------
__global__ void segsum_kernel(const int* __restrict__ cids) {
    __shared__ float ssum[NSEG];
    __shared__ int   scnt[NSEG];
    const int tid = threadIdx.x;
    if (tid < NSEG) { ssum[tid] = 0.0f; scnt[tid] = 0; }
    __syncthreads();
    for (int m = blockIdx.x * blockDim.x + tid; m < MTOT; m += gridDim.x * blockDim.x) {
        int cid = cids[m];
        cid = min(max(cid, 0), CC);
        int seg = (m >> 14) * NCLUST + cid;
        float ex = expf(g_A[m] - g_segmax[seg]);
        g_ex[m] = ex;
        atomicAdd(&ssum[seg], ex);
        atomicAdd(&scnt[seg], 1);
    }
    __syncthreads();
    if (tid < NSEG) {
        atomicAdd(&g_segsum[tid], ssum[tid]);
        atomicAdd(&g_counts[tid], scnt[tid]);
    }
}

// ---------------- kernel 5: cfraw[seg] += w * x[m] ----------------
__global__ __launch_bounds__(256) void cfeat_kernel(const int* __restrict__ cids) {
    __shared__ float sh[NCLUST][IDIM];
    const int tid = threadIdx.x;
    const int b     = blockIdx.x >> 6;
    const int chunk = blockIdx.x & 63;
    for (int i = tid; i < NCLUST * IDIM; i += 256) ((float*)sh)[i] = 0.0f;
    __syncthreads();
    const int mbase = b * NPB + chunk * 256;
    for (int r = 0; r < 256; r++) {
        int m = mbase + r;
        int cid = cids[m];
        cid = min(max(cid, 0), CC);
        float w = g_ex[m] / g_segsum[b * NCLUST + cid];
        const float* xr = &g_x[(size_t)m * IDIM];
        sh[cid][tid]       += w * xr[tid];
        sh[cid][tid + 256] += w * xr[tid + 256];
    }
    __syncthreads();
    for (int c = 0; c < NCLUST; c++) {
        atomicAdd(&g_cfraw[(b * NCLUST + c) * IDIM + tid],       sh[c][tid]);
        atomicAdd(&g_cfraw[(b * NCLUST + c) * IDIM + tid + 256], sh[c][tid + 256]);
    }
}

// ---------------- kernel 6: cfeat = relu(cfraw @ W_intra + b_intra)  [88,512] ----------------
__global__ __launch_bounds__(256) void intra_kernel(
    const float* __restrict__ Wi, const float* __restrict__ bi)
{
    __shared__ float xr[IDIM];
    const int s = blockIdx.x, tid = threadIdx.x;
    xr[tid]       = g_cfraw[s * IDIM + tid];
    xr[tid + 256] = g_cfraw[s * IDIM + tid + 256];
    __syncthreads();
#pragma unroll
    for (int jj = 0; jj < 2; jj++) {
        int j = tid + jj * 256;
        float acc = bi[j];
        for (int k = 0; k < IDIM; k++) acc += xr[k] * Wi[(size_t)k * IDIM + j];
        g_cfeat[s * IDIM + j] = fmaxf(acc, 0.0f);
    }
}

// ---------------- kernel 7: inter-cluster gated logits A2[88] ----------------
__global__ __launch_bounds__(256) void attn2_kernel(
    const float* __restrict__ Wa2, const float* __restrict__ ba2,
    const float* __restrict__ Wb2, const float* __restrict__ bb2,
    const float* __restrict__ Wc2, const float* __restrict__ bc2)
{
    __shared__ float xr[IDIM];
    __shared__ float red[256];
    const int s = blockIdx.x, tid = threadIdx.x;
    xr[tid]       = g_cfeat[s * IDIM + tid];
    xr[tid + 256] = g_cfeat[s * IDIM + tid + 256];
    __syncthreads();
    float aa = ba2[tid], bb = bb2[tid];
    for (int k = 0; k < IDIM; k++) {
        float xv = xr[k];
        aa += xv * Wa2[(size_t)k * DDIM + tid];
        bb += xv * Wb2[(size_t)k * DDIM + tid];
    }
    red[tid] = tanhf(aa) * sigmoidf_(bb) * Wc2[tid];
    __syncthreads();
    for (int off = 128; off > 0; off >>= 1) {
        if (tid < off) red[tid] += red[tid + off];
        __syncthreads();
    }
    if (tid == 0)
        g_A2[s] = (g_counts[s] > 0) ? (red[0] + bc2[0]) : -1e30f;
}

// ---------------- kernel 8: per-batch softmax, pooling, classifier ----------------
__global__ __launch_bounds__(256) void final_kernel(
    const float* __restrict__ Wint, const float* __restrict__ bint,
    const float* __restrict__ Wcls, const float* __restrict__ bcls,
    float* __restrict__ out)
{
    __shared__ float sWs[NCLUST];
    __shared__ float sl[IDIM];
    __shared__ float st2[256];
    __shared__ float red[256];
    const int b = blockIdx.x, tid = threadIdx.x;

    if (tid == 0) {
        float mx = -1e30f;
        for (int c = 0; c < NCLUST; c++) mx = fmaxf(mx, g_A2[b * NCLUST + c]);
        float e[NCLUST]; float sum = 0.0f;
        for (int c = 0; c < NCLUST; c++) { e[c] = expf(g_A2[b * NCLUST + c] - mx); sum += e[c]; }
        for (int c = 0; c < NCLUST; c++) sWs[c] = e[c] / sum;
    }
    __syncthreads();

#pragma unroll
    for (int jj = 0; jj < 2; jj++) {
        int j = tid + jj * 256;
        float s = 0.0f;
        for (int c = 0; c < NCLUST; c++)
            s += sWs[c] * g_cfeat[(b * NCLUST + c) * IDIM + j];
        sl[j] = s;
    }
    __syncthreads();

    float acc = bint[tid];
    for (int k = 0; k < IDIM; k++) acc += sl[k] * Wint[(size_t)k * 256 + tid];
    st2[tid] = fmaxf(acc, 0.0f);
    __syncthreads();

    red[tid] = st2[tid] * Wcls[tid * 2 + 0];
    __syncthreads();
    for (int off = 128; off > 0; off >>= 1) {
        if (tid < off) red[tid] += red[tid + off];
        __syncthreads();
    }
    if (tid == 0) out[b * 2 + 0] = red[0] + bcls[0];
    __syncthreads();

    red[tid] = st2[tid] * Wcls[tid * 2 + 1];
    __syncthreads();
    for (int off = 128; off > 0; off >>= 1) {
        if (tid < off) red[tid] += red[tid + off];
        __syncthreads();
    }
    if (tid == 0) out[b * 2 + 1] = red[0] + bcls[1];
}

// ---------------- launch ----------------
extern "C" void kernel_launch(void* const* d_in, const int* in_sizes, int n_in,
                              void* d_out, int out_size)
{
    const float* h       = (const float*)d_in[0];
    const int*   cids    = (const int*)  d_in[1];
    const float* emb     = (const float*)d_in[2];
    const float* W_fuse  = (const float*)d_in[3];
    const float* b_fuse  = (const float*)d_in[4];
    const float* Wa1     = (const float*)d_in[5];
    const float* ba1     = (const float*)d_in[6];
    const float* Wb1     = (const float*)d_in[7];
    const float* bb1     = (const float*)d_in[8];
    const float* Wc1     = (const float*)d_in[9];
    // d_in[10] = bc1 (softmax-invariant, dropped)
    const float* W_intra = (const float*)d_in[11];
    const float* b_intra = (const float*)d_in[12];
    const float* Wa2     = (const float*)d_in[13];
    const float* ba2     = (const float*)d_in[14];
    const float* Wb2     = (const float*)d_in[15];
    const float* bb2     = (const float*)d_in[16];
    const float* Wc2     = (const float*)d_in[17];
    const float* bc2     = (const float*)d_in[18];
    const float* W_inter = (const float*)d_in[19];
    const float* b_inter = (const float*)d_in[20];
    const float* W_cls   = (const float*)d_in[21];
    const float* b_cls   = (const float*)d_in[22];
    float* out = (float*)d_out;

    // unconditional (no static guard — harness rule); host-side attr set, capture-safe, idempotent
    cudaFuncSetAttribute(fuse_mma_kernel,
                         cudaFuncAttributeMaxDynamicSharedMemorySize, F_DSMEM_BYTES);
    cudaFuncSetAttribute(attn1_mma_kernel,
                         cudaFuncAttributeMaxDynamicSharedMemorySize, A_DSMEM_BYTES);

    init_kernel<<<256, 256>>>(W_fuse, Wa1, Wb1);
    fuse_mma_kernel<<<dim3(IDIM / 128, MTOT / 128), 256, F_DSMEM_BYTES>>>(h, cids, emb, W_fuse, b_fuse);
    attn1_mma_kernel<<<dim3(DDIM / 64, MTOT / 128), 256, A_DSMEM_BYTES>>>(ba1, bb1, Wc1);
    segmax_kernel<<<256, 256>>>(cids);
    segsum_kernel<<<256, 256>>>(cids);
    cfeat_kernel<<<BATCH * 64, 256>>>(cids);
    intra_kernel<<<NSEG, 256>>>(W_intra, b_intra);
    attn2_kernel<<<NSEG, 256>>>(Wa2, ba2, Wb2, bb2, Wc2, bc2);
    final_kernel<<<BATCH, 256>>>(W_inter, b_inter, W_cls, b_cls, out);
}

// round 9
// speedup vs baseline: 1.5570x; 1.5570x over previous
#include <cuda_runtime.h>
#include <cuda_fp16.h>
#include <math.h>
#include <stdint.h>

// ---------------- problem constants ----------------
#define CC     10
#define NCLUST 11            // C+1
#define NSEG   88            // B * (C+1)
#define BATCH  8
#define NPB    16384         // tokens per batch
#define MTOT   131072        // B*N
#define IDIM   512
#define EMBD   8
#define DDIM   256

// ---------------- scratch (static device globals) ----------------
__device__ __half g_h16[(size_t)MTOT * IDIM];    // h in fp16 (rn), 128 MiB
__device__ __half g_x16[(size_t)MTOT * IDIM];    // fused features in fp16
__device__ __half g_Wf16[IDIM * IDIM];           // W_fuse[0:512] transposed [n][k]
__device__ __half g_Wa16[DDIM * IDIM];           // Wa1 transposed [d][k]
__device__ __half g_Wb16[DDIM * IDIM];           // Wb1 transposed [d][k]
__device__ float  g_embW[NCLUST * IDIM];         // bias + emb@Wfuse[512:520] per (cid, n)
__device__ float  g_A[MTOT];                     // intra logits (bc1 dropped: softmax-invariant)
__device__ float  g_ex[MTOT];
__device__ float  g_segmax[NSEG];
__device__ float  g_segsum[NSEG];
__device__ int    g_counts[NSEG];
__device__ float  g_cfraw[NSEG * IDIM];
__device__ float  g_cfeat[NSEG * IDIM];
__device__ float  g_A2[NSEG];

// ---------------- helpers ----------------
__device__ __forceinline__ void atomicMaxFloat(float* addr, float val) {
    int* ia = (int*)addr;
    int old = *ia;
    while (__int_as_float(old) < val) {
        int assumed = old;
        old = atomicCAS(ia, assumed, __float_as_int(val));
        if (old == assumed) break;
    }
}
__device__ __forceinline__ float sigmoidf_(float v) { return 1.0f / (1.0f + expf(-v)); }

__device__ __forceinline__ uint32_t smem_u32(const void* p) {
    return (uint32_t)__cvta_generic_to_shared(p);
}
__device__ __forceinline__ void cp16(uint32_t dst, const void* src) {
    asm volatile("cp.async.cg.shared.global [%0], [%1], 16;" :: "r"(dst), "l"(src));
}
#define CP_COMMIT()  asm volatile("cp.async.commit_group;")
#define CP_WAIT2()   asm volatile("cp.async.wait_group 2;")
#define CP_WAIT1()   asm volatile("cp.async.wait_group 1;")
#define CP_WAIT0()   asm volatile("cp.async.wait_group 0;")

// m16n8k16 fp16 mma, row.col, fp32 accum (rn-rounded fp16 operands -> unbiased)
__device__ __forceinline__ void mma_f16(float* d, const uint32_t* a, const uint32_t* b) {
    asm volatile(
        "mma.sync.aligned.m16n8k16.row.col.f32.f16.f16.f32 "
        "{%0,%1,%2,%3}, {%4,%5,%6,%7}, {%8,%9}, {%0,%1,%2,%3};\n"
        : "+f"(d[0]), "+f"(d[1]), "+f"(d[2]), "+f"(d[3])
        : "r"(a[0]), "r"(a[1]), "r"(a[2]), "r"(a[3]), "r"(b[0]), "r"(b[1]));
}

// smem geometry: rows padded to 40 halves (80 B) -> frag bank = 20*gid + tig, conflict-free
#define ROW_H   40
#define ROW_B   80
#define STAGE_B 20480        // fuse: A 128x40h (10240) + B 128x40h; attn1: A + Ba 64x40h + Bb 64x40h

// ---------------- kernel 0: init ----------------
__global__ void init_kernel() {
    int gtid = blockIdx.x * blockDim.x + threadIdx.x;
    int stride = gridDim.x * blockDim.x;
    for (int i = gtid; i < MTOT; i += stride) g_A[i] = 0.0f;
    for (int i = gtid; i < NSEG * IDIM; i += stride) g_cfraw[i] = 0.0f;
    if (gtid < NSEG) { g_segmax[gtid] = -1e30f; g_segsum[gtid] = 0.0f; g_counts[gtid] = 0; }
}

// ---------------- prepass: h -> fp16 (rn) ----------------
__global__ void prep_h_kernel(const float* __restrict__ h) {
    size_t n4 = (size_t)MTOT * IDIM / 4;
    size_t stride = (size_t)gridDim.x * blockDim.x;
    for (size_t i = (size_t)blockIdx.x * blockDim.x + threadIdx.x; i < n4; i += stride) {
        float4 v = ((const float4*)h)[i];
        ((__half2*)g_h16)[i * 2 + 0] = __floats2half2_rn(v.x, v.y);
        ((__half2*)g_h16)[i * 2 + 1] = __floats2half2_rn(v.z, v.w);
    }
}

// ---------------- prepass: transposed fp16 weights + embW table ----------------
__global__ void prep_w_kernel(const float* __restrict__ Wf, const float* __restrict__ bf,
                              const float* __restrict__ emb,
                              const float* __restrict__ Wa1, const float* __restrict__ Wb1) {
    int gtid = blockIdx.x * blockDim.x + threadIdx.x;
    int stride = gridDim.x * blockDim.x;
    for (int i = gtid; i < IDIM * IDIM; i += stride) {
        int n = i >> 9, k = i & 511;
        g_Wf16[i] = __float2half_rn(Wf[(size_t)k * IDIM + n]);
    }
    for (int i = gtid; i < DDIM * IDIM; i += stride) {
        int d = i >> 9, k = i & 511;
        g_Wa16[i] = __float2half_rn(Wa1[(size_t)k * DDIM + d]);
        g_Wb16[i] = __float2half_rn(Wb1[(size_t)k * DDIM + d]);
    }
    for (int i = gtid; i < NCLUST * IDIM; i += stride) {
        int c = i >> 9, n = i & 511;
        float v = bf[n];
#pragma unroll
        for (int e = 0; e < EMBD; e++)
            v += emb[c * EMBD + e] * Wf[(size_t)(IDIM + e) * IDIM + n];
        g_embW[i] = v;
    }
}

// ---------------- kernel 1: x = relu([h | emb] @ W_fuse + b)  (fp16 mma) ----------------
// block 128(M) x 128(N), 8 warps 4x2 -> warp 32x64, BK=32 halves, 3-stage cp.async ring.
__global__ __launch_bounds__(256, 2) void fuse_f16_kernel(const int* __restrict__ cids) {
    extern __shared__ uint8_t dsm[];
    __shared__ float sEmbW[NCLUST * 128];
    __shared__ int   scids[128];

    const int tid  = threadIdx.x;
    const int n0   = blockIdx.x * 128;
    const int m0   = blockIdx.y * 128;
    const int warp = tid >> 5, lane = tid & 31;
    const int gid  = lane >> 2, tig = lane & 3;
    const int wm   = (warp >> 1) * 32, wn = (warp & 1) * 64;
    const uint32_t ub = smem_u32(dsm);

    if (tid < 128) { int c = cids[m0 + tid]; scids[tid] = min(max(c, 0), CC); }
    for (int t = tid; t < NCLUST * 128; t += 256) {
        int c = t >> 7, j = t & 127;
        sEmbW[t] = g_embW[c * IDIM + n0 + j];
    }

    float acc[2][8][4];
#pragma unroll
    for (int mi = 0; mi < 2; mi++)
#pragma unroll
        for (int ni = 0; ni < 8; ni++)
#pragma unroll
            for (int c = 0; c < 4; c++) acc[mi][ni][c] = 0.0f;

    auto load_slab = [&](int kt, int st) {
        const int k0 = kt * 32;
        const uint32_t sb = ub + st * STAGE_B;
#pragma unroll
        for (int i = 0; i < 2; i++) {                 // A: 128 rows x 4 chunks
            int idx = i * 256 + tid;
            int row = idx >> 2, ch = idx & 3;
            cp16(sb + row * ROW_B + ch * 16,
                 g_h16 + (size_t)(m0 + row) * IDIM + k0 + ch * 8);
        }
#pragma unroll
        for (int i = 0; i < 2; i++) {                 // B: 128 n-rows x 4 chunks
            int idx = i * 256 + tid;
            int row = idx >> 2, ch = idx & 3;
            cp16(sb + 10240 + row * ROW_B + ch * 16,
                 g_Wf16 + (size_t)(n0 + row) * IDIM + k0 + ch * 8);
        }
    };

    load_slab(0, 0); CP_COMMIT();
    load_slab(1, 1); CP_COMMIT();

    for (int kt = 0; kt < 16; kt++) {
        const int cur = kt % 3;
        if (kt < 14)       { load_slab(kt + 2, (kt + 2) % 3); CP_COMMIT(); CP_WAIT2(); }
        else if (kt == 14) { CP_WAIT1(); }
        else               { CP_WAIT0(); }
        __syncthreads();
        const __half* sA = (const __half*)(dsm + cur * STAGE_B);
        const __half* sB = (const __half*)(dsm + cur * STAGE_B + 10240);
#pragma unroll
        for (int ks = 0; ks < 2; ks++) {
            const int ch = ks * 16 + 2 * tig;
            uint32_t af[2][4], bfr[8][2];
#pragma unroll
            for (int mi = 0; mi < 2; mi++) {
                int r = wm + mi * 16 + gid;
                af[mi][0] = *(const uint32_t*)&sA[r * ROW_H + ch];
                af[mi][1] = *(const uint32_t*)&sA[(r + 8) * ROW_H + ch];
                af[mi][2] = *(const uint32_t*)&sA[r * ROW_H + ch + 8];
                af[mi][3] = *(const uint32_t*)&sA[(r + 8) * ROW_H + ch + 8];
            }
#pragma unroll
            for (int ni = 0; ni < 8; ni++) {
                int n = wn + ni * 8 + gid;
                bfr[ni][0] = *(const uint32_t*)&sB[n * ROW_H + ch];
                bfr[ni][1] = *(const uint32_t*)&sB[n * ROW_H + ch + 8];
            }
#pragma unroll
            for (int mi = 0; mi < 2; mi++)
#pragma unroll
                for (int ni = 0; ni < 8; ni++)
                    mma_f16(acc[mi][ni], af[mi], bfr[ni]);
        }
        __syncthreads();
    }

    // epilogue: + embW(cid,n) (bias+emb folded), relu, store fp16
#pragma unroll
    for (int mi = 0; mi < 2; mi++) {
#pragma unroll
        for (int half = 0; half < 2; half++) {
            int ml = wm + mi * 16 + gid + half * 8;
            int m  = m0 + ml;
            const float* ew = &sEmbW[scids[ml] * 128];
#pragma unroll
            for (int ni = 0; ni < 8; ni++) {
                int nl = wn + ni * 8 + 2 * tig;
                float o0 = fmaxf(acc[mi][ni][half * 2 + 0] + ew[nl],     0.0f);
                float o1 = fmaxf(acc[mi][ni][half * 2 + 1] + ew[nl + 1], 0.0f);
                *(__half2*)&g_x16[(size_t)m * IDIM + n0 + nl] = __floats2half2_rn(o0, o1);
            }
        }
    }
}

// ---------------- kernel 2: intra gated attention logits (dual fp16 mma) ----------------
// block 128(M) x 64(D) per d-tile; warp 32x32, computes x@Wa1 and x@Wb1 together.
__global__ __launch_bounds__(256, 2) void attn1_f16_kernel(
    const float* __restrict__ ba1, const float* __restrict__ bb1,
    const float* __restrict__ Wc1) {
    extern __shared__ uint8_t dsm[];
    __shared__ float sba[64], sbb[64], swc[64];
    __shared__ float sA[128];

    const int tid  = threadIdx.x;
    const int d0   = blockIdx.x * 64;
    const int m0   = blockIdx.y * 128;
    const int warp = tid >> 5, lane = tid & 31;
    const int gid  = lane >> 2, tig = lane & 3;
    const int wm   = (warp >> 1) * 32, wn = (warp & 1) * 32;
    const uint32_t ub = smem_u32(dsm);

    if (tid < 64) { sba[tid] = ba1[d0 + tid]; sbb[tid] = bb1[d0 + tid]; swc[tid] = Wc1[d0 + tid]; }
    if (tid < 128) sA[tid] = 0.0f;

    float acca[2][4][4], accg[2][4][4];
#pragma unroll
    for (int mi = 0; mi < 2; mi++)
#pragma unroll
        for (int ni = 0; ni < 4; ni++)
#pragma unroll
            for (int c = 0; c < 4; c++) { acca[mi][ni][c] = 0.0f; accg[mi][ni][c] = 0.0f; }

    auto load_slab = [&](int kt, int st) {
        const int k0 = kt * 32;
        const uint32_t sb = ub + st * STAGE_B;
#pragma unroll
        for (int i = 0; i < 2; i++) {                 // A (x): 128 rows x 4 chunks
            int idx = i * 256 + tid;
            int row = idx >> 2, ch = idx & 3;
            cp16(sb + row * ROW_B + ch * 16,
                 g_x16 + (size_t)(m0 + row) * IDIM + k0 + ch * 8);
        }
        {                                              // Ba: 64 rows x 4 chunks (1/thread)
            int row = tid >> 2, ch = tid & 3;
            cp16(sb + 10240 + row * ROW_B + ch * 16,
                 g_Wa16 + (size_t)(d0 + row) * IDIM + k0 + ch * 8);
            cp16(sb + 15360 + row * ROW_B + ch * 16,
                 g_Wb16 + (size_t)(d0 + row) * IDIM + k0 + ch * 8);
        }
    };

    load_slab(0, 0); CP_COMMIT();
    load_slab(1, 1); CP_COMMIT();

    for (int kt = 0; kt < 16; kt++) {
        const int cur = kt % 3;
        if (kt < 14)       { load_slab(kt + 2, (kt + 2) % 3); CP_COMMIT(); CP_WAIT2(); }
        else if (kt == 14) { CP_WAIT1(); }
        else               { CP_WAIT0(); }
        __syncthreads();
        const __half* sAx = (const __half*)(dsm + cur * STAGE_B);
        const __half* sBa = (const __half*)(dsm + cur * STAGE_B + 10240);
        const __half* sBb = (const __half*)(dsm + cur * STAGE_B + 15360);
#pragma unroll
        for (int ks = 0; ks < 2; ks++) {
            const int ch = ks * 16 + 2 * tig;
            uint32_t af[2][4];
#pragma unroll
            for (int mi = 0; mi < 2; mi++) {
                int r = wm + mi * 16 + gid;
                af[mi][0] = *(const uint32_t*)&sAx[r * ROW_H + ch];
                af[mi][1] = *(const uint32_t*)&sAx[(r + 8) * ROW_H + ch];
                af[mi][2] = *(const uint32_t*)&sAx[r * ROW_H + ch + 8];
                af[mi][3] = *(const uint32_t*)&sAx[(r + 8) * ROW_H + ch + 8];
            }
#pragma unroll
            for (int ni = 0; ni < 4; ni++) {
                int n = wn + ni * 8 + gid;
                uint32_t ba_[2], bb_[2];
                ba_[0] = *(const uint32_t*)&sBa[n * ROW_H + ch];
                ba_[1] = *(const uint32_t*)&sBa[n * ROW_H + ch + 8];
                bb_[0] = *(const uint32_t*)&sBb[n * ROW_H + ch];
                bb_[1] = *(const uint32_t*)&sBb[n * ROW_H + ch + 8];
#pragma unroll
                for (int mi = 0; mi < 2; mi++) {
                    mma_f16(acca[mi][ni], af[mi], ba_);
                    mma_f16(accg[mi][ni], af[mi], bb_);
                }
            }
        }
        __syncthreads();
    }

    // epilogue: gated pointwise + row reduction over this 64-d slab
    float rsum[2][2];
    rsum[0][0] = rsum[0][1] = rsum[1][0] = rsum[1][1] = 0.0f;
#pragma unroll
    for (int mi = 0; mi < 2; mi++)
#pragma unroll
        for (int ni = 0; ni < 4; ni++) {
            int nl = wn + ni * 8 + 2 * tig;
#pragma unroll
            for (int half = 0; half < 2; half++) {
#pragma unroll
                for (int col = 0; col < 2; col++) {
                    int dl = nl + col;
                    float va = tanhf(acca[mi][ni][half * 2 + col] + sba[dl]);
                    float vg = sigmoidf_(accg[mi][ni][half * 2 + col] + sbb[dl]);
                    rsum[mi][half] += va * vg * swc[dl];
                }
            }
        }
#pragma unroll
    for (int mi = 0; mi < 2; mi++)
#pragma unroll
        for (int half = 0; half < 2; half++) {
            float v = rsum[mi][half];
            v += __shfl_xor_sync(0xffffffffu, v, 1);
            v += __shfl_xor_sync(0xffffffffu, v, 2);
            if (tig == 0) atomicAdd(&sA[wm + mi * 16 + gid + half * 8], v);
        }
    __syncthreads();
    if (tid < 128) atomicAdd(&g_A[m0 + tid], sA[tid]);
}

// ---------------- kernel 3: segment max ----------------
__global__ void segmax_kernel(const int* __restrict__ cids) {
    __shared__ float smax[NSEG];
    const int tid = threadIdx.x;
    if (tid < NSEG) smax[tid] = -1e30f;
    __syncthreads();
    for (int m = blockIdx.x * blockDim.x + tid; m < MTOT; m += gridDim.x * blockDim.x) {
        int cid = cids[m];
        cid = min(max(cid, 0), CC);
        int seg = (m >> 14) * NCLUST + cid;
        atomicMaxFloat(&smax[seg], g_A[m]);
    }
    __syncthreads();
    if (tid < NSEG) atomicMaxFloat(&g_segmax[tid], smax[tid]);
}

// ---------------- kernel 4: ex = exp(A - segmax), segment sum + counts ----------------
__global__ void segsum_kernel(const int* __restrict__ cids) {
    __shared__ float ssum[NSEG];
    __shared__ int   scnt[NSEG];
    const int tid = threadIdx.x;
    if (tid < NSEG) { ssum[tid] = 0.0f; scnt[tid] = 0; }
    __syncthreads();
    for (int m = blockIdx.x * blockDim.x + tid; m < MTOT; m += gridDim.x * blockDim.x) {
        int cid = cids[m];
        cid = min(max(cid, 0), CC);
        int seg = (m >> 14) * NCLUST + cid;
        float ex = expf(g_A[m] - g_segmax[seg]);
        g_ex[m] = ex;
        atomicAdd(&ssum[seg], ex);
        atomicAdd(&scnt[seg], 1);
    }
    __syncthreads();
    if (tid < NSEG) {
        atomicAdd(&g_segsum[tid], ssum[tid]);
        atomicAdd(&g_counts[tid], scnt[tid]);
    }
}

// ---------------- kernel 5: cfraw[seg] += w * x[m]  (x in fp16) ----------------
__global__ __launch_bounds__(256) void cfeat_kernel(const int* __restrict__ cids) {
    __shared__ float sh[NCLUST][IDIM];
    const int tid = threadIdx.x;
    const int b     = blockIdx.x >> 6;
    const int chunk = blockIdx.x & 63;
    for (int i = tid; i < NCLUST * IDIM; i += 256) ((float*)sh)[i] = 0.0f;
    __syncthreads();
    const int mbase = b * NPB + chunk * 256;
    for (int r = 0; r < 256; r++) {
        int m = mbase + r;
        int cid = cids[m];
        cid = min(max(cid, 0), CC);
        float w = g_ex[m] / g_segsum[b * NCLUST + cid];
        const __half* xr = &g_x16[(size_t)m * IDIM];
        sh[cid][tid]       += w * __half2float(xr[tid]);
        sh[cid][tid + 256] += w * __half2float(xr[tid + 256]);
    }
    __syncthreads();
    for (int c = 0; c < NCLUST; c++) {
        atomicAdd(&g_cfraw[(b * NCLUST + c) * IDIM + tid],       sh[c][tid]);
        atomicAdd(&g_cfraw[(b * NCLUST + c) * IDIM + tid + 256], sh[c][tid + 256]);
    }
}

// ---------------- kernel 6: cfeat = relu(cfraw @ W_intra + b_intra)  [88,512] ----------------
__global__ __launch_bounds__(256) void intra_kernel(
    const float* __restrict__ Wi, const float* __restrict__ bi)
{
    __shared__ float xr[IDIM];
    const int s = blockIdx.x, tid = threadIdx.x;
    xr[tid]       = g_cfraw[s * IDIM + tid];
    xr[tid + 256] = g_cfraw[s * IDIM + tid + 256];
    __syncthreads();
#pragma unroll
    for (int jj = 0; jj < 2; jj++) {
        int j = tid + jj * 256;
        float acc = bi[j];
        for (int k = 0; k < IDIM; k++) acc += xr[k] * Wi[(size_t)k * IDIM + j];
        g_cfeat[s * IDIM + j] = fmaxf(acc, 0.0f);
    }
}

// ---------------- kernel 7: inter-cluster gated logits A2[88] ----------------
__global__ __launch_bounds__(256) void attn2_kernel(
    const float* __restrict__ Wa2, const float* __restrict__ ba2,
    const float* __restrict__ Wb2, const float* __restrict__ bb2,
    const float* __restrict__ Wc2, const float* __restrict__ bc2)
{
    __shared__ float xr[IDIM];
    __shared__ float red[256];
    const int s = blockIdx.x, tid = threadIdx.x;
    xr[tid]       = g_cfeat[s * IDIM + tid];
    xr[tid + 256] = g_cfeat[s * IDIM + tid + 256];
    __syncthreads();
    float aa = ba2[tid], bb = bb2[tid];
    for (int k = 0; k < IDIM; k++) {
        float xv = xr[k];
        aa += xv * Wa2[(size_t)k * DDIM + tid];
        bb += xv * Wb2[(size_t)k * DDIM + tid];
    }
    red[tid] = tanhf(aa) * sigmoidf_(bb) * Wc2[tid];
    __syncthreads();
    for (int off = 128; off > 0; off >>= 1) {
        if (tid < off) red[tid] += red[tid + off];
        __syncthreads();
    }
    if (tid == 0)
        g_A2[s] = (g_counts[s] > 0) ? (red[0] + bc2[0]) : -1e30f;
}

// ---------------- kernel 8: per-batch softmax, pooling, classifier ----------------
__global__ __launch_bounds__(256) void final_kernel(
    const float* __restrict__ Wint, const float* __restrict__ bint,
    const float* __restrict__ Wcls, const float* __restrict__ bcls,
    float* __restrict__ out)
{
    __shared__ float sWs[NCLUST];
    __shared__ float sl[IDIM];
    __shared__ float st2[256];
    __shared__ float red[256];
    const int b = blockIdx.x, tid = threadIdx.x;

    if (tid == 0) {
        float mx = -1e30f;
        for (int c = 0; c < NCLUST; c++) mx = fmaxf(mx, g_A2[b * NCLUST + c]);
        float e[NCLUST]; float sum = 0.0f;
        for (int c = 0; c < NCLUST; c++) { e[c] = expf(g_A2[b * NCLUST + c] - mx); sum += e[c]; }
        for (int c = 0; c < NCLUST; c++) sWs[c] = e[c] / sum;
    }
    __syncthreads();

#pragma unroll
    for (int jj = 0; jj < 2; jj++) {
        int j = tid + jj * 256;
        float s = 0.0f;
        for (int c = 0; c < NCLUST; c++)
            s += sWs[c] * g_cfeat[(b * NCLUST + c) * IDIM + j];
        sl[j] = s;
    }
    __syncthreads();

    float acc = bint[tid];
    for (int k = 0; k < IDIM; k++) acc += sl[k] * Wint[(size_t)k * 256 + tid];
    st2[tid] = fmaxf(acc, 0.0f);
    __syncthreads();

    red[tid] = st2[tid] * Wcls[tid * 2 + 0];
    __syncthreads();
    for (int off = 128; off > 0; off >>= 1) {
        if (tid < off) red[tid] += red[tid + off];
        __syncthreads();
    }
    if (tid == 0) out[b * 2 + 0] = red[0] + bcls[0];
    __syncthreads();

    red[tid] = st2[tid] * Wcls[tid * 2 + 1];
    __syncthreads();
    for (int off = 128; off > 0; off >>= 1) {
        if (tid < off) red[tid] += red[tid + off];
        __syncthreads();
    }
    if (tid == 0) out[b * 2 + 1] = red[0] + bcls[1];
}

// ---------------- launch ----------------
#define GEMM_DSMEM (3 * STAGE_B)

extern "C" void kernel_launch(void* const* d_in, const int* in_sizes, int n_in,
                              void* d_out, int out_size)
{
    const float* h       = (const float*)d_in[0];
    const int*   cids    = (const int*)  d_in[1];
    const float* emb     = (const float*)d_in[2];
    const float* W_fuse  = (const float*)d_in[3];
    const float* b_fuse  = (const float*)d_in[4];
    const float* Wa1     = (const float*)d_in[5];
    const float* ba1     = (const float*)d_in[6];
    const float* Wb1     = (const float*)d_in[7];
    const float* bb1     = (const float*)d_in[8];
    const float* Wc1     = (const float*)d_in[9];
    // d_in[10] = bc1 (softmax-invariant, dropped)
    const float* W_intra = (const float*)d_in[11];
    const float* b_intra = (const float*)d_in[12];
    const float* Wa2     = (const float*)d_in[13];
    const float* ba2     = (const float*)d_in[14];
    const float* Wb2     = (const float*)d_in[15];
    const float* bb2     = (const float*)d_in[16];
    const float* Wc2     = (const float*)d_in[17];
    const float* bc2     = (const float*)d_in[18];
    const float* W_inter = (const float*)d_in[19];
    const float* b_inter = (const float*)d_in[20];
    const float* W_cls   = (const float*)d_in[21];
    const float* b_cls   = (const float*)d_in[22];
    float* out = (float*)d_out;

    // unconditional host attr sets (no static guards; capture-safe; idempotent)
    cudaFuncSetAttribute(fuse_f16_kernel,  cudaFuncAttributeMaxDynamicSharedMemorySize, GEMM_DSMEM);
    cudaFuncSetAttribute(attn1_f16_kernel, cudaFuncAttributeMaxDynamicSharedMemorySize, GEMM_DSMEM);

    init_kernel<<<256, 256>>>();
    prep_h_kernel<<<1024, 256>>>(h);
    prep_w_kernel<<<256, 256>>>(W_fuse, b_fuse, emb, Wa1, Wb1);
    fuse_f16_kernel<<<dim3(IDIM / 128, MTOT / 128), 256, GEMM_DSMEM>>>(cids);
    attn1_f16_kernel<<<dim3(DDIM / 64, MTOT / 128), 256, GEMM_DSMEM>>>(ba1, bb1, Wc1);
    segmax_kernel<<<256, 256>>>(cids);
    segsum_kernel<<<256, 256>>>(cids);
    cfeat_kernel<<<BATCH * 64, 256>>>(cids);
    intra_kernel<<<NSEG, 256>>>(W_intra, b_intra);
    attn2_kernel<<<NSEG, 256>>>(Wa2, ba2, Wb2, bb2, Wc2, bc2);
    final_kernel<<<BATCH, 256>>>(W_inter, b_inter, W_cls, b_cls, out);
}

// round 10
// speedup vs baseline: 1.6224x; 1.0420x over previous
#include <cuda_runtime.h>
#include <cuda_fp16.h>
#include <math.h>
#include <stdint.h>

// ---------------- problem constants ----------------
#define CC     10
#define NCLUST 11            // C+1
#define NSEG   88            // B * (C+1)
#define BATCH  8
#define NPB    16384         // tokens per batch
#define MTOT   131072        // B*N
#define IDIM   512
#define EMBD   8
#define DDIM   256

// ---------------- scratch (static device globals) ----------------
__device__ __half g_h16[(size_t)MTOT * IDIM];    // h in fp16 (rn)
__device__ __half g_x16[(size_t)MTOT * IDIM];    // fused features in fp16
__device__ __half g_Wf16[IDIM * IDIM];           // W_fuse[0:512] transposed [n][k]
__device__ __half g_Wa16[DDIM * IDIM];           // Wa1 transposed [d][k]
__device__ __half g_Wb16[DDIM * IDIM];           // Wb1 transposed [d][k]
__device__ float  g_embW[NCLUST * IDIM];         // bias + emb@Wfuse[512:520] per (cid, n)
__device__ float  g_A[MTOT];                     // intra logits (bc1 dropped: softmax-invariant)
__device__ float  g_ex[MTOT];
__device__ float  g_segmax[NSEG];
__device__ float  g_segsum[NSEG];
__device__ int    g_counts[NSEG];
__device__ float  g_cfraw[NSEG * IDIM];
__device__ float  g_cfeat[NSEG * IDIM];
__device__ float  g_A2[NSEG];

// ---------------- helpers ----------------
__device__ __forceinline__ void atomicMaxFloat(float* addr, float val) {
    int* ia = (int*)addr;
    int old = *ia;
    while (__int_as_float(old) < val) {
        int assumed = old;
        old = atomicCAS(ia, assumed, __float_as_int(val));
        if (old == assumed) break;
    }
}
__device__ __forceinline__ float sigmoidf_(float v) { return 1.0f / (1.0f + expf(-v)); }

__device__ __forceinline__ uint32_t smem_u32(const void* p) {
    return (uint32_t)__cvta_generic_to_shared(p);
}
__device__ __forceinline__ void cp16(uint32_t dst, const void* src) {
    asm volatile("cp.async.cg.shared.global [%0], [%1], 16;" :: "r"(dst), "l"(src));
}
#define CP_COMMIT()  asm volatile("cp.async.commit_group;")
#define CP_WAIT2()   asm volatile("cp.async.wait_group 2;")
#define CP_WAIT1()   asm volatile("cp.async.wait_group 1;")
#define CP_WAIT0()   asm volatile("cp.async.wait_group 0;")

// m16n8k16 fp16 mma, row.col, fp32 accum
__device__ __forceinline__ void mma_f16(float* d, const uint32_t* a, const uint32_t* b) {
    asm volatile(
        "mma.sync.aligned.m16n8k16.row.col.f32.f16.f16.f32 "
        "{%0,%1,%2,%3}, {%4,%5,%6,%7}, {%8,%9}, {%0,%1,%2,%3};\n"
        : "+f"(d[0]), "+f"(d[1]), "+f"(d[2]), "+f"(d[3])
        : "r"(a[0]), "r"(a[1]), "r"(a[2]), "r"(a[3]), "r"(b[0]), "r"(b[1]));
}

// ldmatrix x4 (non-trans): 4 m8n8 b16 tiles; per-8-lane-group addresses
__device__ __forceinline__ void ldsm_x4(uint32_t* r, uint32_t addr) {
    asm volatile("ldmatrix.sync.aligned.m8n8.x4.shared.b16 {%0,%1,%2,%3}, [%4];"
                 : "=r"(r[0]), "=r"(r[1]), "=r"(r[2]), "=r"(r[3]) : "r"(addr));
}

// smem geometry: rows padded to 40 halves (80 B); ldmatrix row bank-quads disjoint
#define ROW_H   40
#define ROW_B   80
#define STAGE_B 20480        // fuse: A 128x40h + B 128x40h; attn1: A + Ba 64x40h + Bb 64x40h
#define GEMM_DSMEM (3 * STAGE_B)

// ---------------- kernel 0: init ----------------
__global__ void init_kernel() {
    int gtid = blockIdx.x * blockDim.x + threadIdx.x;
    int stride = gridDim.x * blockDim.x;
    for (int i = gtid; i < MTOT; i += stride) g_A[i] = 0.0f;
    for (int i = gtid; i < NSEG * IDIM; i += stride) g_cfraw[i] = 0.0f;
    if (gtid < NSEG) { g_segmax[gtid] = -1e30f; g_segsum[gtid] = 0.0f; g_counts[gtid] = 0; }
}

// ---------------- prepass: h -> fp16 (rn) ----------------
__global__ void prep_h_kernel(const float* __restrict__ h) {
    size_t n4 = (size_t)MTOT * IDIM / 4;
    size_t stride = (size_t)gridDim.x * blockDim.x;
    for (size_t i = (size_t)blockIdx.x * blockDim.x + threadIdx.x; i < n4; i += stride) {
        float4 v = ((const float4*)h)[i];
        ((__half2*)g_h16)[i * 2 + 0] = __floats2half2_rn(v.x, v.y);
        ((__half2*)g_h16)[i * 2 + 1] = __floats2half2_rn(v.z, v.w);
    }
}

// ---------------- prepass: transposed fp16 weights + embW table ----------------
__global__ void prep_w_kernel(const float* __restrict__ Wf, const float* __restrict__ bf,
                              const float* __restrict__ emb,
                              const float* __restrict__ Wa1, const float* __restrict__ Wb1) {
    int gtid = blockIdx.x * blockDim.x + threadIdx.x;
    int stride = gridDim.x * blockDim.x;
    for (int i = gtid; i < IDIM * IDIM; i += stride) {
        int n = i >> 9, k = i & 511;
        g_Wf16[i] = __float2half_rn(Wf[(size_t)k * IDIM + n]);
    }
    for (int i = gtid; i < DDIM * IDIM; i += stride) {
        int d = i >> 9, k = i & 511;
        g_Wa16[i] = __float2half_rn(Wa1[(size_t)k * DDIM + d]);
        g_Wb16[i] = __float2half_rn(Wb1[(size_t)k * DDIM + d]);
    }
    for (int i = gtid; i < NCLUST * IDIM; i += stride) {
        int c = i >> 9, n = i & 511;
        float v = bf[n];
#pragma unroll
        for (int e = 0; e < EMBD; e++)
            v += emb[c * EMBD + e] * Wf[(size_t)(IDIM + e) * IDIM + n];
        g_embW[i] = v;
    }
}

// ---------------- kernel 1: x = relu([h | emb] @ W_fuse + b)  (fp16 mma, ldmatrix) ----------------
// 128 threads (4 warps 2x2), warp tile 64x64, BK=32, 3-stage cp.async ring.
__global__ __launch_bounds__(128, 2) void fuse_f16_kernel(const int* __restrict__ cids) {
    extern __shared__ uint8_t dsm[];
    __shared__ float sEmbW[NCLUST * 128];
    __shared__ int   scids[128];

    const int tid  = threadIdx.x;
    const int n0   = blockIdx.x * 128;
    const int m0   = blockIdx.y * 128;
    const int warp = tid >> 5, lane = tid & 31;
    const int gid  = lane >> 2, tig = lane & 3;
    const int wm   = (warp >> 1) * 64, wn = (warp & 1) * 64;
    const uint32_t ub = smem_u32(dsm);

    // ldmatrix lane addressing
    const int a_row = lane & 15;                 // A: group rows
    const int a_k   = (lane >> 4) << 3;          // 0 | 8
    const int b_row = (lane & 7) + ((lane >> 4) << 3);   // B: n-row within 16
    const int b_k   = ((lane >> 3) & 1) << 3;            // 0 | 8

    if (tid < 128) { int c = cids[m0 + tid]; scids[tid] = min(max(c, 0), CC); }
    for (int t = tid; t < NCLUST * 128; t += 128) {
        int c = t >> 7, j = t & 127;
        sEmbW[t] = g_embW[c * IDIM + n0 + j];
    }

    float acc[4][8][4];
#pragma unroll
    for (int mi = 0; mi < 4; mi++)
#pragma unroll
        for (int ni = 0; ni < 8; ni++)
#pragma unroll
            for (int c = 0; c < 4; c++) acc[mi][ni][c] = 0.0f;

    auto load_slab = [&](int kt, int st) {
        const int k0 = kt * 32;
        const uint32_t sb = ub + st * STAGE_B;
#pragma unroll
        for (int i = 0; i < 4; i++) {                 // A: 128 rows x 4 chunks
            int idx = i * 128 + tid;
            int row = idx >> 2, ch = idx & 3;
            cp16(sb + row * ROW_B + ch * 16,
                 g_h16 + (size_t)(m0 + row) * IDIM + k0 + ch * 8);
        }
#pragma unroll
        for (int i = 0; i < 4; i++) {                 // B: 128 n-rows x 4 chunks
            int idx = i * 128 + tid;
            int row = idx >> 2, ch = idx & 3;
            cp16(sb + 10240 + row * ROW_B + ch * 16,
                 g_Wf16 + (size_t)(n0 + row) * IDIM + k0 + ch * 8);
        }
    };

    load_slab(0, 0); CP_COMMIT();
    load_slab(1, 1); CP_COMMIT();

    for (int kt = 0; kt < 16; kt++) {
        const int cur = kt % 3;
        if (kt < 14)       { load_slab(kt + 2, (kt + 2) % 3); CP_COMMIT(); CP_WAIT2(); }
        else if (kt == 14) { CP_WAIT1(); }
        else               { CP_WAIT0(); }
        __syncthreads();
        const uint32_t sa = ub + cur * STAGE_B;
        const uint32_t sb = sa + 10240;
#pragma unroll
        for (int ks = 0; ks < 2; ks++) {
            uint32_t af[4][4], bfr[8][2];
#pragma unroll
            for (int mi = 0; mi < 4; mi++)
                ldsm_x4(af[mi], sa + (wm + mi * 16 + a_row) * ROW_B + (ks * 16 + a_k) * 2);
#pragma unroll
            for (int nj = 0; nj < 4; nj++)
                ldsm_x4(&bfr[2 * nj][0], sb + (wn + nj * 16 + b_row) * ROW_B + (ks * 16 + b_k) * 2);
#pragma unroll
            for (int mi = 0; mi < 4; mi++)
#pragma unroll
                for (int ni = 0; ni < 8; ni++)
                    mma_f16(acc[mi][ni], af[mi], bfr[ni]);
        }
        __syncthreads();
    }

    // epilogue: + embW(cid,n) (bias+emb folded), relu, store fp16
#pragma unroll
    for (int mi = 0; mi < 4; mi++) {
#pragma unroll
        for (int half = 0; half < 2; half++) {
            int ml = wm + mi * 16 + gid + half * 8;
            int m  = m0 + ml;
            const float* ew = &sEmbW[scids[ml] * 128];
#pragma unroll
            for (int ni = 0; ni < 8; ni++) {
                int nl = wn + ni * 8 + 2 * tig;
                float o0 = fmaxf(acc[mi][ni][half * 2 + 0] + ew[nl],     0.0f);
                float o1 = fmaxf(acc[mi][ni][half * 2 + 1] + ew[nl + 1], 0.0f);
                *(__half2*)&g_x16[(size_t)m * IDIM + n0 + nl] = __floats2half2_rn(o0, o1);
            }
        }
    }
}

// ---------------- kernel 2: intra gated attention logits (dual fp16 mma, ldmatrix) ----------------
// 128 threads (4 warps 2x2), warp tile 64 rows x 32 d, both a and g per warp.
__global__ __launch_bounds__(128, 2) void attn1_f16_kernel(
    const float* __restrict__ ba1, const float* __restrict__ bb1,
    const float* __restrict__ Wc1) {
    extern __shared__ uint8_t dsm[];
    __shared__ float sba[64], sbb[64], swc[64];
    __shared__ float sA[128];

    const int tid  = threadIdx.x;
    const int d0   = blockIdx.x * 64;
    const int m0   = blockIdx.y * 128;
    const int warp = tid >> 5, lane = tid & 31;
    const int gid  = lane >> 2, tig = lane & 3;
    const int wm   = (warp >> 1) * 64, wn = (warp & 1) * 32;
    const uint32_t ub = smem_u32(dsm);

    const int a_row = lane & 15;
    const int a_k   = (lane >> 4) << 3;
    const int b_row = (lane & 7) + ((lane >> 4) << 3);
    const int b_k   = ((lane >> 3) & 1) << 3;

    if (tid < 64) { sba[tid] = ba1[d0 + tid]; sbb[tid] = bb1[d0 + tid]; swc[tid] = Wc1[d0 + tid]; }
    if (tid < 128) sA[tid] = 0.0f;

    float acca[4][4][4], accg[4][4][4];
#pragma unroll
    for (int mi = 0; mi < 4; mi++)
#pragma unroll
        for (int ni = 0; ni < 4; ni++)
#pragma unroll
            for (int c = 0; c < 4; c++) { acca[mi][ni][c] = 0.0f; accg[mi][ni][c] = 0.0f; }

    auto load_slab = [&](int kt, int st) {
        const int k0 = kt * 32;
        const uint32_t sb = ub + st * STAGE_B;
#pragma unroll
        for (int i = 0; i < 4; i++) {                 // A (x): 128 rows x 4 chunks
            int idx = i * 128 + tid;
            int row = idx >> 2, ch = idx & 3;
            cp16(sb + row * ROW_B + ch * 16,
                 g_x16 + (size_t)(m0 + row) * IDIM + k0 + ch * 8);
        }
#pragma unroll
        for (int i = 0; i < 2; i++) {                 // Ba: 64 rows x 4 chunks
            int idx = i * 128 + tid;
            int row = idx >> 2, ch = idx & 3;
            cp16(sb + 10240 + row * ROW_B + ch * 16,
                 g_Wa16 + (size_t)(d0 + row) * IDIM + k0 + ch * 8);
        }
#pragma unroll
        for (int i = 0; i < 2; i++) {                 // Bb: 64 rows x 4 chunks
            int idx = i * 128 + tid;
            int row = idx >> 2, ch = idx & 3;
            cp16(sb + 15360 + row * ROW_B + ch * 16,
                 g_Wb16 + (size_t)(d0 + row) * IDIM + k0 + ch * 8);
        }
    };

    load_slab(0, 0); CP_COMMIT();
    load_slab(1, 1); CP_COMMIT();

    for (int kt = 0; kt < 16; kt++) {
        const int cur = kt % 3;
        if (kt < 14)       { load_slab(kt + 2, (kt + 2) % 3); CP_COMMIT(); CP_WAIT2(); }
        else if (kt == 14) { CP_WAIT1(); }
        else               { CP_WAIT0(); }
        __syncthreads();
        const uint32_t sax = ub + cur * STAGE_B;
        const uint32_t sba_ = sax + 10240;
        const uint32_t sbb_ = sax + 15360;
#pragma unroll
        for (int ks = 0; ks < 2; ks++) {
            uint32_t af[4][4], ba_[4][2], bb_[4][2];
#pragma unroll
            for (int mi = 0; mi < 4; mi++)
                ldsm_x4(af[mi], sax + (wm + mi * 16 + a_row) * ROW_B + (ks * 16 + a_k) * 2);
#pragma unroll
            for (int nj = 0; nj < 2; nj++) {
                ldsm_x4(&ba_[2 * nj][0], sba_ + (wn + nj * 16 + b_row) * ROW_B + (ks * 16 + b_k) * 2);
                ldsm_x4(&bb_[2 * nj][0], sbb_ + (wn + nj * 16 + b_row) * ROW_B + (ks * 16 + b_k) * 2);
            }
#pragma unroll
            for (int mi = 0; mi < 4; mi++)
#pragma unroll
                for (int ni = 0; ni < 4; ni++) {
                    mma_f16(acca[mi][ni], af[mi], ba_[ni]);
                    mma_f16(accg[mi][ni], af[mi], bb_[ni]);
                }
        }
        __syncthreads();
    }

    // epilogue: gated pointwise + row reduction over this 64-d slab
    float rsum[4][2];
#pragma unroll
    for (int mi = 0; mi < 4; mi++) { rsum[mi][0] = 0.0f; rsum[mi][1] = 0.0f; }
#pragma unroll
    for (int mi = 0; mi < 4; mi++)
#pragma unroll
        for (int ni = 0; ni < 4; ni++) {
            int nl = wn + ni * 8 + 2 * tig;
#pragma unroll
            for (int half = 0; half < 2; half++) {
#pragma unroll
                for (int col = 0; col < 2; col++) {
                    int dl = nl + col;
                    float va = tanhf(acca[mi][ni][half * 2 + col] + sba[dl]);
                    float vg = sigmoidf_(accg[mi][ni][half * 2 + col] + sbb[dl]);
                    rsum[mi][half] += va * vg * swc[dl];
                }
            }
        }
#pragma unroll
    for (int mi = 0; mi < 4; mi++)
#pragma unroll
        for (int half = 0; half < 2; half++) {
            float v = rsum[mi][half];
            v += __shfl_xor_sync(0xffffffffu, v, 1);
            v += __shfl_xor_sync(0xffffffffu, v, 2);
            if (tig == 0) atomicAdd(&sA[wm + mi * 16 + gid + half * 8], v);
        }
    __syncthreads();
    if (tid < 128) atomicAdd(&g_A[m0 + tid], sA[tid]);
}

// ---------------- kernel 3: segment max ----------------
__global__ void segmax_kernel(const int* __restrict__ cids) {
    __shared__ float smax[NSEG];
    const int tid = threadIdx.x;
    if (tid < NSEG) smax[tid] = -1e30f;
    __syncthreads();
    for (int m = blockIdx.x * blockDim.x + tid; m < MTOT; m += gridDim.x * blockDim.x) {
        int cid = cids[m];
        cid = min(max(cid, 0), CC);
        int seg = (m >> 14) * NCLUST + cid;
        atomicMaxFloat(&smax[seg], g_A[m]);
    }
    __syncthreads();
    if (tid < NSEG) atomicMaxFloat(&g_segmax[tid], smax[tid]);
}

// ---------------- kernel 4: ex = exp(A - segmax), segment sum + counts ----------------
__global__ void segsum_kernel(const int* __restrict__ cids) {
    __shared__ float ssum[NSEG];
    __shared__ int   scnt[NSEG];
    const int tid = threadIdx.x;
    if (tid < NSEG) { ssum[tid] = 0.0f; scnt[tid] = 0; }
    __syncthreads();
    for (int m = blockIdx.x * blockDim.x + tid; m < MTOT; m += gridDim.x * blockDim.x) {
        int cid = cids[m];
        cid = min(max(cid, 0), CC);
        int seg = (m >> 14) * NCLUST + cid;
        float ex = expf(g_A[m] - g_segmax[seg]);
        g_ex[m] = ex;
        atomicAdd(&ssum[seg], ex);
        atomicAdd(&scnt[seg], 1);
    }
    __syncthreads();
    if (tid < NSEG) {
        atomicAdd(&g_segsum[tid], ssum[tid]);
        atomicAdd(&g_counts[tid], scnt[tid]);
    }
}

// ---------------- kernel 5: cfraw[seg] += w * x[m]  (x in fp16) ----------------
__global__ __launch_bounds__(256) void cfeat_kernel(const int* __restrict__ cids) {
    __shared__ float sh[NCLUST][IDIM];
    const int tid = threadIdx.x;
    const int b     = blockIdx.x >> 6;
    const int chunk = blockIdx.x & 63;
    for (int i = tid; i < NCLUST * IDIM; i += 256) ((float*)sh)[i] = 0.0f;
    __syncthreads();
    const int mbase = b * NPB + chunk * 256;
    for (int r = 0; r < 256; r++) {
        int m = mbase + r;
        int cid = cids[m];
        cid = min(max(cid, 0), CC);
        float w = g_ex[m] / g_segsum[b * NCLUST + cid];
        const __half* xr = &g_x16[(size_t)m * IDIM];
        sh[cid][tid]       += w * __half2float(xr[tid]);
        sh[cid][tid + 256] += w * __half2float(xr[tid + 256]);
    }
    __syncthreads();
    for (int c = 0; c < NCLUST; c++) {
        atomicAdd(&g_cfraw[(b * NCLUST + c) * IDIM + tid],       sh[c][tid]);
        atomicAdd(&g_cfraw[(b * NCLUST + c) * IDIM + tid + 256], sh[c][tid + 256]);
    }
}

// ---------------- kernel 6: cfeat = relu(cfraw @ W_intra + b_intra)  [88,512] ----------------
__global__ __launch_bounds__(256) void intra_kernel(
    const float* __restrict__ Wi, const float* __restrict__ bi)
{
    __shared__ float xr[IDIM];
    const int s = blockIdx.x, tid = threadIdx.x;
    xr[tid]       = g_cfraw[s * IDIM + tid];
    xr[tid + 256] = g_cfraw[s * IDIM + tid + 256];
    __syncthreads();
#pragma unroll
    for (int jj = 0; jj < 2; jj++) {
        int j = tid + jj * 256;
        float acc = bi[j];
        for (int k = 0; k < IDIM; k++) acc += xr[k] * Wi[(size_t)k * IDIM + j];
        g_cfeat[s * IDIM + j] = fmaxf(acc, 0.0f);
    }
}

// ---------------- kernel 7: inter-cluster gated logits A2[88] ----------------
__global__ __launch_bounds__(256) void attn2_kernel(
    const float* __restrict__ Wa2, const float* __restrict__ ba2,
    const float* __restrict__ Wb2, const float* __restrict__ bb2,
    const float* __restrict__ Wc2, const float* __restrict__ bc2)
{
    __shared__ float xr[IDIM];
    __shared__ float red[256];
    const int s = blockIdx.x, tid = threadIdx.x;
    xr[tid]       = g_cfeat[s * IDIM + tid];
    xr[tid + 256] = g_cfeat[s * IDIM + tid + 256];
    __syncthreads();
    float aa = ba2[tid], bb = bb2[tid];
    for (int k = 0; k < IDIM; k++) {
        float xv = xr[k];
        aa += xv * Wa2[(size_t)k * DDIM + tid];
        bb += xv * Wb2[(size_t)k * DDIM + tid];
    }
    red[tid] = tanhf(aa) * sigmoidf_(bb) * Wc2[tid];
    __syncthreads();
    for (int off = 128; off > 0; off >>= 1) {
        if (tid < off) red[tid] += red[tid + off];
        __syncthreads();
    }
    if (tid == 0)
        g_A2[s] = (g_counts[s] > 0) ? (red[0] + bc2[0]) : -1e30f;
}

// ---------------- kernel 8: per-batch softmax, pooling, classifier ----------------
__global__ __launch_bounds__(256) void final_kernel(
    const float* __restrict__ Wint, const float* __restrict__ bint,
    const float* __restrict__ Wcls, const float* __restrict__ bcls,
    float* __restrict__ out)
{
    __shared__ float sWs[NCLUST];
    __shared__ float sl[IDIM];
    __shared__ float st2[256];
    __shared__ float red[256];
    const int b = blockIdx.x, tid = threadIdx.x;

    if (tid == 0) {
        float mx = -1e30f;
        for (int c = 0; c < NCLUST; c++) mx = fmaxf(mx, g_A2[b * NCLUST + c]);
        float e[NCLUST]; float sum = 0.0f;
        for (int c = 0; c < NCLUST; c++) { e[c] = expf(g_A2[b * NCLUST + c] - mx); sum += e[c]; }
        for (int c = 0; c < NCLUST; c++) sWs[c] = e[c] / sum;
    }
    __syncthreads();

#pragma unroll
    for (int jj = 0; jj < 2; jj++) {
        int j = tid + jj * 256;
        float s = 0.0f;
        for (int c = 0; c < NCLUST; c++)
            s += sWs[c] * g_cfeat[(b * NCLUST + c) * IDIM + j];
        sl[j] = s;
    }
    __syncthreads();

    float acc = bint[tid];
    for (int k = 0; k < IDIM; k++) acc += sl[k] * Wint[(size_t)k * 256 + tid];
    st2[tid] = fmaxf(acc, 0.0f);
    __syncthreads();

    red[tid] = st2[tid] * Wcls[tid * 2 + 0];
    __syncthreads();
    for (int off = 128; off > 0; off >>= 1) {
        if (tid < off) red[tid] += red[tid + off];
        __syncthreads();
    }
    if (tid == 0) out[b * 2 + 0] = red[0] + bcls[0];
    __syncthreads();

    red[tid] = st2[tid] * Wcls[tid * 2 + 1];
    __syncthreads();
    for (int off = 128; off > 0; off >>= 1) {
        if (tid < off) red[tid] += red[tid + off];
        __syncthreads();
    }
    if (tid == 0) out[b * 2 + 1] = red[0] + bcls[1];
}

// ---------------- launch ----------------
extern "C" void kernel_launch(void* const* d_in, const int* in_sizes, int n_in,
                              void* d_out, int out_size)
{
    const float* h       = (const float*)d_in[0];
    const int*   cids    = (const int*)  d_in[1];
    const float* emb     = (const float*)d_in[2];
    const float* W_fuse  = (const float*)d_in[3];
    const float* b_fuse  = (const float*)d_in[4];
    const float* Wa1     = (const float*)d_in[5];
    const float* ba1     = (const float*)d_in[6];
    const float* Wb1     = (const float*)d_in[7];
    const float* bb1     = (const float*)d_in[8];
    const float* Wc1     = (const float*)d_in[9];
    // d_in[10] = bc1 (softmax-invariant, dropped)
    const float* W_intra = (const float*)d_in[11];
    const float* b_intra = (const float*)d_in[12];
    const float* Wa2     = (const float*)d_in[13];
    const float* ba2     = (const float*)d_in[14];
    const float* Wb2     = (const float*)d_in[15];
    const float* bb2     = (const float*)d_in[16];
    const float* Wc2     = (const float*)d_in[17];
    const float* bc2     = (const float*)d_in[18];
    const float* W_inter = (const float*)d_in[19];
    const float* b_inter = (const float*)d_in[20];
    const float* W_cls   = (const float*)d_in[21];
    const float* b_cls   = (const float*)d_in[22];
    float* out = (float*)d_out;

    // unconditional host attr sets (no static guards; capture-safe; idempotent)
    cudaFuncSetAttribute(fuse_f16_kernel,  cudaFuncAttributeMaxDynamicSharedMemorySize, GEMM_DSMEM);
    cudaFuncSetAttribute(attn1_f16_kernel, cudaFuncAttributeMaxDynamicSharedMemorySize, GEMM_DSMEM);

    init_kernel<<<256, 256>>>();
    prep_h_kernel<<<1024, 256>>>(h);
    prep_w_kernel<<<256, 256>>>(W_fuse, b_fuse, emb, Wa1, Wb1);
    fuse_f16_kernel<<<dim3(IDIM / 128, MTOT / 128), 128, GEMM_DSMEM>>>(cids);
    attn1_f16_kernel<<<dim3(DDIM / 64, MTOT / 128), 128, GEMM_DSMEM>>>(ba1, bb1, Wc1);
    segmax_kernel<<<256, 256>>>(cids);
    segsum_kernel<<<256, 256>>>(cids);
    cfeat_kernel<<<BATCH * 64, 256>>>(cids);
    intra_kernel<<<NSEG, 256>>>(W_intra, b_intra);
    attn2_kernel<<<NSEG, 256>>>(Wa2, ba2, Wb2, bb2, Wc2, bc2);
    final_kernel<<<BATCH, 256>>>(W_inter, b_inter, W_cls, b_cls, out);
}

// round 13
// speedup vs baseline: 2.2859x; 1.4089x over previous
#include <cuda_runtime.h>
#include <cuda_fp16.h>
#include <math.h>
#include <stdint.h>

// ---------------- problem constants ----------------
#define CC     10
#define NCLUST 11            // C+1
#define NSEG   88            // B * (C+1)
#define BATCH  8
#define NPB    16384         // tokens per batch
#define MTOT   131072        // B*N
#define IDIM   512
#define EMBD   8
#define DDIM   256

// ---------------- scratch (static device globals) ----------------
__device__ __half g_h16[(size_t)MTOT * IDIM];    // h in fp16 (rn)
__device__ __half g_x16[(size_t)MTOT * IDIM];    // fused features in fp16
__device__ __half g_Wf16[IDIM * IDIM];           // W_fuse[0:512] transposed [n][k]
__device__ __half g_Wa16[DDIM * IDIM];           // Wa1 transposed [d][k]
__device__ __half g_Wb16[DDIM * IDIM];           // Wb1 transposed [d][k]
__device__ float  g_embW[NCLUST * IDIM];         // bias + emb@Wfuse[512:520] per (cid, n)
__device__ float  g_A[MTOT];                     // intra logits (bc1 dropped: softmax-invariant)
__device__ float  g_ex[MTOT];
__device__ float  g_segmax[NSEG];
__device__ float  g_segsum[NSEG];
__device__ int    g_counts[NSEG];
__device__ float  g_cfraw[NSEG * IDIM];
__device__ float  g_cfeat[NSEG * IDIM];
__device__ float  g_A2[NSEG];

// ---------------- helpers ----------------
__device__ __forceinline__ void atomicMaxFloat(float* addr, float val) {
    int* ia = (int*)addr;
    int old = *ia;
    while (__int_as_float(old) < val) {
        int assumed = old;
        old = atomicCAS(ia, assumed, __float_as_int(val));
        if (old == assumed) break;
    }
}
__device__ __forceinline__ float sigmoidf_(float v) { return 1.0f / (1.0f + expf(-v)); }

__device__ __forceinline__ uint32_t smem_u32(const void* p) {
    return (uint32_t)__cvta_generic_to_shared(p);
}
__device__ __forceinline__ void cp16(uint32_t dst, const void* src) {
    asm volatile("cp.async.cg.shared.global [%0], [%1], 16;" :: "r"(dst), "l"(src));
}
#define CP_COMMIT()  asm volatile("cp.async.commit_group;")
#define CP_WAIT3()   asm volatile("cp.async.wait_group 3;")
#define CP_WAIT2()   asm volatile("cp.async.wait_group 2;")
#define CP_WAIT1()   asm volatile("cp.async.wait_group 1;")
#define CP_WAIT0()   asm volatile("cp.async.wait_group 0;")

// m16n8k16 fp16 mma, row.col, fp32 accum
__device__ __forceinline__ void mma_f16(float* d, const uint32_t* a, const uint32_t* b) {
    asm volatile(
        "mma.sync.aligned.m16n8k16.row.col.f32.f16.f16.f32 "
        "{%0,%1,%2,%3}, {%4,%5,%6,%7}, {%8,%9}, {%0,%1,%2,%3};\n"
        : "+f"(d[0]), "+f"(d[1]), "+f"(d[2]), "+f"(d[3])
        : "r"(a[0]), "r"(a[1]), "r"(a[2]), "r"(a[3]), "r"(b[0]), "r"(b[1]));
}

// ldmatrix x4 (non-trans): 4 m8n8 b16 tiles
__device__ __forceinline__ void ldsm_x4(uint32_t* r, uint32_t addr) {
    asm volatile("ldmatrix.sync.aligned.m8n8.x4.shared.b16 {%0,%1,%2,%3}, [%4];"
                 : "=r"(r[0]), "=r"(r[1]), "=r"(r[2]), "=r"(r[3]) : "r"(addr));
}

// smem geometry: rows padded to 40 halves (80 B); ldmatrix row bank-quads disjoint
#define ROW_H   40
#define ROW_B   80
#define STAGE_B 20480        // fuse: A 128x40h + B 128x40h; attn1: A + Ba 64x40h + Bb 64x40h
#define GEMM_DSMEM (4 * STAGE_B)

// ---------------- kernel 0: init ----------------
__global__ void init_kernel() {
    int gtid = blockIdx.x * blockDim.x + threadIdx.x;
    int stride = gridDim.x * blockDim.x;
    for (int i = gtid; i < MTOT; i += stride) g_A[i] = 0.0f;
    for (int i = gtid; i < NSEG * IDIM; i += stride) g_cfraw[i] = 0.0f;
    if (gtid < NSEG) { g_segmax[gtid] = -1e30f; g_segsum[gtid] = 0.0f; g_counts[gtid] = 0; }
}

// ---------------- prepass: h -> fp16 (rn) ----------------
__global__ void prep_h_kernel(const float* __restrict__ h) {
    size_t n4 = (size_t)MTOT * IDIM / 4;
    size_t stride = (size_t)gridDim.x * blockDim.x;
    for (size_t i = (size_t)blockIdx.x * blockDim.x + threadIdx.x; i < n4; i += stride) {
        float4 v = ((const float4*)h)[i];
        ((__half2*)g_h16)[i * 2 + 0] = __floats2half2_rn(v.x, v.y);
        ((__half2*)g_h16)[i * 2 + 1] = __floats2half2_rn(v.z, v.w);
    }
}

// ---------------- prepass: transposed fp16 weights + embW table ----------------
__global__ void prep_w_kernel(const float* __restrict__ Wf, const float* __restrict__ bf,
                              const float* __restrict__ emb,
                              const float* __restrict__ Wa1, const float* __restrict__ Wb1) {
    int gtid = blockIdx.x * blockDim.x + threadIdx.x;
    int stride = gridDim.x * blockDim.x;
    for (int i = gtid; i < IDIM * IDIM; i += stride) {
        int n = i >> 9, k = i & 511;
        g_Wf16[i] = __float2half_rn(Wf[(size_t)k * IDIM + n]);
    }
    for (int i = gtid; i < DDIM * IDIM; i += stride) {
        int d = i >> 9, k = i & 511;
        g_Wa16[i] = __float2half_rn(Wa1[(size_t)k * DDIM + d]);
        g_Wb16[i] = __float2half_rn(Wb1[(size_t)k * DDIM + d]);
    }
    for (int i = gtid; i < NCLUST * IDIM; i += stride) {
        int c = i >> 9, n = i & 511;
        float v = bf[n];
#pragma unroll
        for (int e = 0; e < EMBD; e++)
            v += emb[c * EMBD + e] * Wf[(size_t)(IDIM + e) * IDIM + n];
        g_embW[i] = v;
    }
}

// ---------------- kernel 1: x = relu([h | emb] @ W_fuse + b)  (fp16 mma, ldmatrix) ----------------
// 256 threads (8 warps 2Mx4N), warp tile 64x32, BK=32, 4-stage cp.async ring, 2 CTAs/SM.
__global__ __launch_bounds__(256, 2) void fuse_f16_kernel(const int* __restrict__ cids) {
    extern __shared__ uint8_t dsm[];
    __shared__ float sEmbW[NCLUST * 128];
    __shared__ int   scids[128];

    const int tid  = threadIdx.x;
    const int n0   = blockIdx.x * 128;
    const int m0   = blockIdx.y * 128;
    const int warp = tid >> 5, lane = tid & 31;
    const int gid  = lane >> 2, tig = lane & 3;
    const int wm   = (warp >> 2) * 64;        // 2 M-groups of 64
    const int wn   = (warp & 3) * 32;         // 4 N-groups of 32
    const uint32_t ub = smem_u32(dsm);

    // ldmatrix lane addressing
    const int a_row = lane & 15;
    const int a_k   = (lane >> 4) << 3;                 // 0 | 8
    const int b_row = (lane & 7) + ((lane >> 4) << 3);  // n-row within 16
    const int b_k   = ((lane >> 3) & 1) << 3;           // 0 | 8

    if (tid < 128) { int c = cids[m0 + tid]; scids[tid] = min(max(c, 0), CC); }
    for (int t = tid; t < NCLUST * 128; t += 256) {
        int c = t >> 7, j = t & 127;
        sEmbW[t] = g_embW[c * IDIM + n0 + j];
    }

    float acc[4][4][4];     // 4 M16-tiles x 4 N8-tiles
#pragma unroll
    for (int mi = 0; mi < 4; mi++)
#pragma unroll
        for (int ni = 0; ni < 4; ni++)
#pragma unroll
            for (int c = 0; c < 4; c++) acc[mi][ni][c] = 0.0f;

    auto load_slab = [&](int kt, int st) {
        const int k0 = kt * 32;
        const uint32_t sb = ub + st * STAGE_B;
#pragma unroll
        for (int i = 0; i < 2; i++) {                 // A: 128 rows x 4 chunks
            int idx = i * 256 + tid;
            int row = idx >> 2, ch = idx & 3;
            cp16(sb + row * ROW_B + ch * 16,
                 g_h16 + (size_t)(m0 + row) * IDIM + k0 + ch * 8);
        }
#pragma unroll
        for (int i = 0; i < 2; i++) {                 // B: 128 n-rows x 4 chunks
            int idx = i * 256 + tid;
            int row = idx >> 2, ch = idx & 3;
            cp16(sb + 10240 + row * ROW_B + ch * 16,
                 g_Wf16 + (size_t)(n0 + row) * IDIM + k0 + ch * 8);
        }
    };

    load_slab(0, 0); CP_COMMIT();
    load_slab(1, 1); CP_COMMIT();
    load_slab(2, 2); CP_COMMIT();

    for (int kt = 0; kt < 16; kt++) {
        const int cur = kt & 3;
        if (kt < 13)       { load_slab(kt + 3, (kt + 3) & 3); CP_COMMIT(); CP_WAIT3(); }
        else if (kt == 13) { CP_WAIT2(); }
        else if (kt == 14) { CP_WAIT1(); }
        else               { CP_WAIT0(); }
        __syncthreads();
        const uint32_t sa = ub + cur * STAGE_B;
        const uint32_t sb = sa + 10240;
#pragma unroll
        for (int ks = 0; ks < 2; ks++) {
            uint32_t af[4][4], bfr[4][2];
#pragma unroll
            for (int mi = 0; mi < 4; mi++)
                ldsm_x4(af[mi], sa + (wm + mi * 16 + a_row) * ROW_B + (ks * 16 + a_k) * 2);
#pragma unroll
            for (int nj = 0; nj < 2; nj++)
                ldsm_x4(&bfr[2 * nj][0], sb + (wn + nj * 16 + b_row) * ROW_B + (ks * 16 + b_k) * 2);
#pragma unroll
            for (int mi = 0; mi < 4; mi++)
#pragma unroll
                for (int ni = 0; ni < 4; ni++)
                    mma_f16(acc[mi][ni], af[mi], bfr[ni]);
        }
        __syncthreads();
    }

    // epilogue: + embW(cid,n) (bias+emb folded), relu, store fp16
#pragma unroll
    for (int mi = 0; mi < 4; mi++) {
#pragma unroll
        for (int half = 0; half < 2; half++) {
            int ml = wm + mi * 16 + gid + half * 8;
            int m  = m0 + ml;
            const float* ew = &sEmbW[scids[ml] * 128];
#pragma unroll
            for (int ni = 0; ni < 4; ni++) {
                int nl = wn + ni * 8 + 2 * tig;
                float o0 = fmaxf(acc[mi][ni][half * 2 + 0] + ew[nl],     0.0f);
                float o1 = fmaxf(acc[mi][ni][half * 2 + 1] + ew[nl + 1], 0.0f);
                *(__half2*)&g_x16[(size_t)m * IDIM + n0 + nl] = __floats2half2_rn(o0, o1);
            }
        }
    }
}

// ---------------- kernel 2: intra gated attention logits (dual fp16 mma, ldmatrix) ----------------
// 256 threads (8 warps 2Mx4D), warp tile 64 rows x 16 d, both a and g per warp.
__global__ __launch_bounds__(256, 2) void attn1_f16_kernel(
    const float* __restrict__ ba1, const float* __restrict__ bb1,
    const float* __restrict__ Wc1) {
    extern __shared__ uint8_t dsm[];
    __shared__ float sba[64], sbb[64], swc[64];
    __shared__ float sA[128];

    const int tid  = threadIdx.x;
    const int d0   = blockIdx.x * 64;
    const int m0   = blockIdx.y * 128;
    const int warp = tid >> 5, lane = tid & 31;
    const int gid  = lane >> 2, tig = lane & 3;
    const int wm   = (warp >> 2) * 64;        // 2 M-groups of 64
    const int wn   = (warp & 3) * 16;         // 4 D-groups of 16
    const uint32_t ub = smem_u32(dsm);

    const int a_row = lane & 15;
    const int a_k   = (lane >> 4) << 3;
    const int b_row = (lane & 7) + ((lane >> 4) << 3);
    const int b_k   = ((lane >> 3) & 1) << 3;

    if (tid < 64) { sba[tid] = ba1[d0 + tid]; sbb[tid] = bb1[d0 + tid]; swc[tid] = Wc1[d0 + tid]; }
    if (tid < 128) sA[tid] = 0.0f;

    float acca[4][2][4], accg[4][2][4];
#pragma unroll
    for (int mi = 0; mi < 4; mi++)
#pragma unroll
        for (int ni = 0; ni < 2; ni++)
#pragma unroll
            for (int c = 0; c < 4; c++) { acca[mi][ni][c] = 0.0f; accg[mi][ni][c] = 0.0f; }

    auto load_slab = [&](int kt, int st) {
        const int k0 = kt * 32;
        const uint32_t sb = ub + st * STAGE_B;
#pragma unroll
        for (int i = 0; i < 2; i++) {                 // A (x): 128 rows x 4 chunks
            int idx = i * 256 + tid;
            int row = idx >> 2, ch = idx & 3;
            cp16(sb + row * ROW_B + ch * 16,
                 g_x16 + (size_t)(m0 + row) * IDIM + k0 + ch * 8);
        }
        // Ba (rows 0..63) then Bb (rows 64..127): 128 rows x 4 chunks = 512 items
#pragma unroll
        for (int i = 0; i < 2; i++) {
            int idx = i * 256 + tid;
            int row = idx >> 2, ch = idx & 3;       // row 0..127
            if (row < 64) {
                cp16(sb + 10240 + row * ROW_B + ch * 16,
                     g_Wa16 + (size_t)(d0 + row) * IDIM + k0 + ch * 8);
            } else {
                int r2 = row - 64;
                cp16(sb + 15360 + r2 * ROW_B + ch * 16,
                     g_Wb16 + (size_t)(d0 + r2) * IDIM + k0 + ch * 8);
            }
        }
    };

    load_slab(0, 0); CP_COMMIT();
    load_slab(1, 1); CP_COMMIT();
    load_slab(2, 2); CP_COMMIT();

    for (int kt = 0; kt < 16; kt++) {
        const int cur = kt & 3;
        if (kt < 13)       { load_slab(kt + 3, (kt + 3) & 3); CP_COMMIT(); CP_WAIT3(); }
        else if (kt == 13) { CP_WAIT2(); }
        else if (kt == 14) { CP_WAIT1(); }
        else               { CP_WAIT0(); }
        __syncthreads();
        const uint32_t sax = ub + cur * STAGE_B;
        const uint32_t sba_ = sax + 10240;
        const uint32_t sbb_ = sax + 15360;
#pragma unroll
        for (int ks = 0; ks < 2; ks++) {
            uint32_t af[4][4], ba_[2][2], bb_[2][2];
#pragma unroll
            for (int mi = 0; mi < 4; mi++)
                ldsm_x4(af[mi], sax + (wm + mi * 16 + a_row) * ROW_B + (ks * 16 + a_k) * 2);
            ldsm_x4(&ba_[0][0], sba_ + (wn + b_row) * ROW_B + (ks * 16 + b_k) * 2);
            ldsm_x4(&bb_[0][0], sbb_ + (wn + b_row) * ROW_B + (ks * 16 + b_k) * 2);
#pragma unroll
            for (int mi = 0; mi < 4; mi++)
#pragma unroll
                for (int ni = 0; ni < 2; ni++) {
                    mma_f16(acca[mi][ni], af[mi], ba_[ni]);
                    mma_f16(accg[mi][ni], af[mi], bb_[ni]);
                }
        }
        __syncthreads();
    }

    // epilogue: gated pointwise + row reduction over this warp's 16-d slice
    float rsum[4][2];
#pragma unroll
    for (int mi = 0; mi < 4; mi++) { rsum[mi][0] = 0.0f; rsum[mi][1] = 0.0f; }
#pragma unroll
    for (int mi = 0; mi < 4; mi++)
#pragma unroll
        for (int ni = 0; ni < 2; ni++) {
            int nl = wn + ni * 8 + 2 * tig;
#pragma unroll
            for (int half = 0; half < 2; half++) {
#pragma unroll
                for (int col = 0; col < 2; col++) {
                    int dl = nl + col;
                    float va = tanhf(acca[mi][ni][half * 2 + col] + sba[dl]);
                    float vg = sigmoidf_(accg[mi][ni][half * 2 + col] + sbb[dl]);
                    rsum[mi][half] += va * vg * swc[dl];
                }
            }
        }
#pragma unroll
    for (int mi = 0; mi < 4; mi++)
#pragma unroll
        for (int half = 0; half < 2; half++) {
            float v = rsum[mi][half];
            v += __shfl_xor_sync(0xffffffffu, v, 1);
            v += __shfl_xor_sync(0xffffffffu, v, 2);
            if (tig == 0) atomicAdd(&sA[wm + mi * 16 + gid + half * 8], v);
        }
    __syncthreads();
    if (tid < 128) atomicAdd(&g_A[m0 + tid], sA[tid]);
}

// ---------------- kernel 3: segment max ----------------
__global__ void segmax_kernel(const int* __restrict__ cids) {
    __shared__ float smax[NSEG];
    const int tid = threadIdx.x;
    if (tid < NSEG) smax[tid] = -1e30f;
    __syncthreads();
    for (int m = blockIdx.x * blockDim.x + tid; m < MTOT; m += gridDim.x * blockDim.x) {
        int cid = cids[m];
        cid = min(max(cid, 0), CC);
        int seg = (m >> 14) * NCLUST + cid;
        atomicMaxFloat(&smax[seg], g_A[m]);
    }
    __syncthreads();
    if (tid < NSEG) atomicMaxFloat(&g_segmax[tid], smax[tid]);
}

// ---------------- kernel 4: ex = exp(A - segmax), segment sum + counts ----------------
__global__ void segsum_kernel(const int* __restrict__ cids) {
    __shared__ float ssum[NSEG];
    __shared__ int   scnt[NSEG];
    const int tid = threadIdx.x;
    if (tid < NSEG) { ssum[tid] = 0.0f; scnt[tid] = 0; }
    __syncthreads();
    for (int m = blockIdx.x * blockDim.x + tid; m < MTOT; m += gridDim.x * blockDim.x) {
        int cid = cids[m];
        cid = min(max(cid, 0), CC);
        int seg = (m >> 14) * NCLUST + cid;
        float ex = expf(g_A[m] - g_segmax[seg]);
        g_ex[m] = ex;
        atomicAdd(&ssum[seg], ex);
        atomicAdd(&scnt[seg], 1);
    }
    __syncthreads();
    if (tid < NSEG) {
        atomicAdd(&g_segsum[tid], ssum[tid]);
        atomicAdd(&g_counts[tid], scnt[tid]);
    }
}

// ---------------- kernel 5: cfraw[seg] += w * x[m]  (x in fp16) ----------------
__global__ __launch_bounds__(256) void cfeat_kernel(const int* __restrict__ cids) {
    __shared__ float sh[NCLUST][IDIM];
    const int tid = threadIdx.x;
    const int b     = blockIdx.x >> 6;
    const int chunk = blockIdx.x & 63;
    for (int i = tid; i < NCLUST * IDIM; i += 256) ((float*)sh)[i] = 0.0f;
    __syncthreads();
    const int mbase = b * NPB + chunk * 256;
    for (int r = 0; r < 256; r++) {
        int m = mbase + r;
        int cid = cids[m];
        cid = min(max(cid, 0), CC);
        float w = g_ex[m] / g_segsum[b * NCLUST + cid];
        const __half* xr = &g_x16[(size_t)m * IDIM];
        sh[cid][tid]       += w * __half2float(xr[tid]);
        sh[cid][tid + 256] += w * __half2float(xr[tid + 256]);
    }
    __syncthreads();
    for (int c = 0; c < NCLUST; c++) {
        atomicAdd(&g_cfraw[(b * NCLUST + c) * IDIM + tid],       sh[c][tid]);
        atomicAdd(&g_cfraw[(b * NCLUST + c) * IDIM + tid + 256], sh[c][tid + 256]);
    }
}

// ---------------- kernel 6: cfeat = relu(cfraw @ W_intra + b_intra)  [88,512] ----------------
__global__ __launch_bounds__(256) void intra_kernel(
    const float* __restrict__ Wi, const float* __restrict__ bi)
{
    __shared__ float xr[IDIM];
    const int s = blockIdx.x, tid = threadIdx.x;
    xr[tid]       = g_cfraw[s * IDIM + tid];
    xr[tid + 256] = g_cfraw[s * IDIM + tid + 256];
    __syncthreads();
#pragma unroll
    for (int jj = 0; jj < 2; jj++) {
        int j = tid + jj * 256;
        float acc = bi[j];
        for (int k = 0; k < IDIM; k++) acc += xr[k] * Wi[(size_t)k * IDIM + j];
        g_cfeat[s * IDIM + j] = fmaxf(acc, 0.0f);
    }
}

// ---------------- kernel 7: inter-cluster gated logits A2[88] ----------------
__global__ __launch_bounds__(256) void attn2_kernel(
    const float* __restrict__ Wa2, const float* __restrict__ ba2,
    const float* __restrict__ Wb2, const float* __restrict__ bb2,
    const float* __restrict__ Wc2, const float* __restrict__ bc2)
{
    __shared__ float xr[IDIM];
    __shared__ float red[256];
    const int s = blockIdx.x, tid = threadIdx.x;
    xr[tid]       = g_cfeat[s * IDIM + tid];
    xr[tid + 256] = g_cfeat[s * IDIM + tid + 256];
    __syncthreads();
    float aa = ba2[tid], bb = bb2[tid];
    for (int k = 0; k < IDIM; k++) {
        float xv = xr[k];
        aa += xv * Wa2[(size_t)k * DDIM + tid];
        bb += xv * Wb2[(size_t)k * DDIM + tid];
    }
    red[tid] = tanhf(aa) * sigmoidf_(bb) * Wc2[tid];
    __syncthreads();
    for (int off = 128; off > 0; off >>= 1) {
        if (tid < off) red[tid] += red[tid + off];
        __syncthreads();
    }
    if (tid == 0)
        g_A2[s] = (g_counts[s] > 0) ? (red[0] + bc2[0]) : -1e30f;
}

// ---------------- kernel 8: per-batch softmax, pooling, classifier ----------------
__global__ __launch_bounds__(256) void final_kernel(
    const float* __restrict__ Wint, const float* __restrict__ bint,
    const float* __restrict__ Wcls, const float* __restrict__ bcls,
    float* __restrict__ out)
{
    __shared__ float sWs[NCLUST];
    __shared__ float sl[IDIM];
    __shared__ float st2[256];
    __shared__ float red[256];
    const int b = blockIdx.x, tid = threadIdx.x;

    if (tid == 0) {
        float mx = -1e30f;
        for (int c = 0; c < NCLUST; c++) mx = fmaxf(mx, g_A2[b * NCLUST + c]);
        float e[NCLUST]; float sum = 0.0f;
        for (int c = 0; c < NCLUST; c++) { e[c] = expf(g_A2[b * NCLUST + c] - mx); sum += e[c]; }
        for (int c = 0; c < NCLUST; c++) sWs[c] = e[c] / sum;
    }
    __syncthreads();

#pragma unroll
    for (int jj = 0; jj < 2; jj++) {
        int j = tid + jj * 256;
        float s = 0.0f;
        for (int c = 0; c < NCLUST; c++)
            s += sWs[c] * g_cfeat[(b * NCLUST + c) * IDIM + j];
        sl[j] = s;
    }
    __syncthreads();

    float acc = bint[tid];
    for (int k = 0; k < IDIM; k++) acc += sl[k] * Wint[(size_t)k * 256 + tid];
    st2[tid] = fmaxf(acc, 0.0f);
    __syncthreads();

    red[tid] = st2[tid] * Wcls[tid * 2 + 0];
    __syncthreads();
    for (int off = 128; off > 0; off >>= 1) {
        if (tid < off) red[tid] += red[tid + off];
        __syncthreads();
    }
    if (tid == 0) out[b * 2 + 0] = red[0] + bcls[0];
    __syncthreads();

    red[tid] = st2[tid] * Wcls[tid * 2 + 1];
    __syncthreads();
    for (int off = 128; off > 0; off >>= 1) {
        if (tid < off) red[tid] += red[tid + off];
        __syncthreads();
    }
    if (tid == 0) out[b * 2 + 1] = red[0] + bcls[1];
}

// ---------------- launch ----------------
extern "C" void kernel_launch(void* const* d_in, const int* in_sizes, int n_in,
                              void* d_out, int out_size)
{
    const float* h       = (const float*)d_in[0];
    const int*   cids    = (const int*)  d_in[1];
    const float* emb     = (const float*)d_in[2];
    const float* W_fuse  = (const float*)d_in[3];
    const float* b_fuse  = (const float*)d_in[4];
    const float* Wa1     = (const float*)d_in[5];
    const float* ba1     = (const float*)d_in[6];
    const float* Wb1     = (const float*)d_in[7];
    const float* bb1     = (const float*)d_in[8];
    const float* Wc1     = (const float*)d_in[9];
    // d_in[10] = bc1 (softmax-invariant, dropped)
    const float* W_intra = (const float*)d_in[11];
    const float* b_intra = (const float*)d_in[12];
    const float* Wa2     = (const float*)d_in[13];
    const float* ba2     = (const float*)d_in[14];
    const float* Wb2     = (const float*)d_in[15];
    const float* bb2     = (const float*)d_in[16];
    const float* Wc2     = (const float*)d_in[17];
    const float* bc2     = (const float*)d_in[18];
    const float* W_inter = (const float*)d_in[19];
    const float* b_inter = (const float*)d_in[20];
    const float* W_cls   = (const float*)d_in[21];
    const float* b_cls   = (const float*)d_in[22];
    float* out = (float*)d_out;

    // unconditional host attr sets (no static guards; capture-safe; idempotent)
    cudaFuncSetAttribute(fuse_f16_kernel,  cudaFuncAttributeMaxDynamicSharedMemorySize, GEMM_DSMEM);
    cudaFuncSetAttribute(attn1_f16_kernel, cudaFuncAttributeMaxDynamicSharedMemorySize, GEMM_DSMEM);

    init_kernel<<<256, 256>>>();
    prep_h_kernel<<<1024, 256>>>(h);
    prep_w_kernel<<<256, 256>>>(W_fuse, b_fuse, emb, Wa1, Wb1);
    fuse_f16_kernel<<<dim3(IDIM / 128, MTOT / 128), 256, GEMM_DSMEM>>>(cids);
    attn1_f16_kernel<<<dim3(DDIM / 64, MTOT / 128), 256, GEMM_DSMEM>>>(ba1, bb1, Wc1);
    segmax_kernel<<<256, 256>>>(cids);
    segsum_kernel<<<256, 256>>>(cids);
    cfeat_kernel<<<BATCH * 64, 256>>>(cids);
    intra_kernel<<<NSEG, 256>>>(W_intra, b_intra);
    attn2_kernel<<<NSEG, 256>>>(Wa2, ba2, Wb2, bb2, Wc2, bc2);
    final_kernel<<<BATCH, 256>>>(W_inter, b_inter, W_cls, b_cls, out);
}

// round 15
// speedup vs baseline: 2.5023x; 1.0947x over previous
#include <cuda_runtime.h>
#include <cuda_fp16.h>
#include <math.h>
#include <stdint.h>

// ---------------- problem constants ----------------
#define CC     10
#define NCLUST 11            // C+1
#define NSEG   88            // B * (C+1)
#define BATCH  8
#define NPB    16384         // tokens per batch
#define MTOT   131072        // B*N
#define IDIM   512
#define EMBD   8
#define DDIM   256

// ---------------- scratch (static device globals) ----------------
__device__ __half g_h16[(size_t)MTOT * IDIM];    // h in fp16 (rn)
__device__ __half g_x16[(size_t)MTOT * IDIM];    // fused features in fp16
__device__ __half g_Wf16[IDIM * IDIM];           // W_fuse[0:512] transposed [n][k]
__device__ __half g_Wa16[DDIM * IDIM];           // Wa1 transposed [d][k]
__device__ __half g_Wb16[DDIM * IDIM];           // Wb1 transposed [d][k]
__device__ float  g_embW[NCLUST * IDIM];         // bias + emb@Wfuse[512:520] per (cid, n)
__device__ float  g_A[MTOT];                     // intra logits (bc1 dropped: softmax-invariant)
__device__ float  g_ex[MTOT];
__device__ float  g_segmax[NSEG];
__device__ float  g_segsum[NSEG];
__device__ int    g_counts[NSEG];
__device__ float  g_cfraw[NSEG * IDIM];
__device__ float  g_cfeat[NSEG * IDIM];
__device__ float  g_A2[NSEG];

// ---------------- helpers ----------------
__device__ __forceinline__ void atomicMaxFloat(float* addr, float val) {
    int* ia = (int*)addr;
    int old = *ia;
    while (__int_as_float(old) < val) {
        int assumed = old;
        old = atomicCAS(ia, assumed, __float_as_int(val));
        if (old == assumed) break;
    }
}
__device__ __forceinline__ float sigmoidf_(float v) { return 1.0f / (1.0f + expf(-v)); }

__device__ __forceinline__ uint32_t smem_u32(const void* p) {
    return (uint32_t)__cvta_generic_to_shared(p);
}
__device__ __forceinline__ void cp16(uint32_t dst, const void* src) {
    asm volatile("cp.async.cg.shared.global [%0], [%1], 16;" :: "r"(dst), "l"(src));
}
#define CP_COMMIT()  asm volatile("cp.async.commit_group;")
#define CP_WAIT2()   asm volatile("cp.async.wait_group 2;")
#define CP_WAIT0()   asm volatile("cp.async.wait_group 0;")

// m16n8k16 fp16 mma, row.col, fp32 accum
__device__ __forceinline__ void mma_f16(float* d, const uint32_t* a, const uint32_t* b) {
    asm volatile(
        "mma.sync.aligned.m16n8k16.row.col.f32.f16.f16.f32 "
        "{%0,%1,%2,%3}, {%4,%5,%6,%7}, {%8,%9}, {%0,%1,%2,%3};\n"
        : "+f"(d[0]), "+f"(d[1]), "+f"(d[2]), "+f"(d[3])
        : "r"(a[0]), "r"(a[1]), "r"(a[2]), "r"(a[3]), "r"(b[0]), "r"(b[1]));
}

// ldmatrix x4 (non-trans): 4 m8n8 b16 tiles
__device__ __forceinline__ void ldsm_x4(uint32_t* r, uint32_t addr) {
    asm volatile("ldmatrix.sync.aligned.m8n8.x4.shared.b16 {%0,%1,%2,%3}, [%4];"
                 : "=r"(r[0]), "=r"(r[1]), "=r"(r[2]), "=r"(r[3]) : "r"(addr));
}

// smem geometry: rows padded to 40 halves (80 B); ldmatrix row bank-quads disjoint
#define ROW_H   40
#define ROW_B   80
#define STAGE_B 20480        // fuse: A 128x40h + B 128x40h; attn1: A + Ba 64x40h + Bb 64x40h
#define GEMM_DSMEM (4 * STAGE_B)

// ---------------- kernel 0: init ----------------
__global__ void init_kernel() {
    int gtid = blockIdx.x * blockDim.x + threadIdx.x;
    int stride = gridDim.x * blockDim.x;
    for (int i = gtid; i < MTOT; i += stride) g_A[i] = 0.0f;
    for (int i = gtid; i < NSEG * IDIM; i += stride) g_cfraw[i] = 0.0f;
    if (gtid < NSEG) { g_segmax[gtid] = -1e30f; g_segsum[gtid] = 0.0f; g_counts[gtid] = 0; }
}

// ---------------- prepass: h -> fp16 (rn) ----------------
__global__ void prep_h_kernel(const float* __restrict__ h) {
    size_t n4 = (size_t)MTOT * IDIM / 4;
    size_t stride = (size_t)gridDim.x * blockDim.x;
    for (size_t i = (size_t)blockIdx.x * blockDim.x + threadIdx.x; i < n4; i += stride) {
        float4 v = ((const float4*)h)[i];
        ((__half2*)g_h16)[i * 2 + 0] = __floats2half2_rn(v.x, v.y);
        ((__half2*)g_h16)[i * 2 + 1] = __floats2half2_rn(v.z, v.w);
    }
}

// ---------------- prepass: transposed fp16 weights + embW table ----------------
__global__ void prep_w_kernel(const float* __restrict__ Wf, const float* __restrict__ bf,
                              const float* __restrict__ emb,
                              const float* __restrict__ Wa1, const float* __restrict__ Wb1) {
    int gtid = blockIdx.x * blockDim.x + threadIdx.x;
    int stride = gridDim.x * blockDim.x;
    for (int i = gtid; i < IDIM * IDIM; i += stride) {
        int n = i >> 9, k = i & 511;
        g_Wf16[i] = __float2half_rn(Wf[(size_t)k * IDIM + n]);
    }
    for (int i = gtid; i < DDIM * IDIM; i += stride) {
        int d = i >> 9, k = i & 511;
        g_Wa16[i] = __float2half_rn(Wa1[(size_t)k * DDIM + d]);
        g_Wb16[i] = __float2half_rn(Wb1[(size_t)k * DDIM + d]);
    }
    for (int i = gtid; i < NCLUST * IDIM; i += stride) {
        int c = i >> 9, n = i & 511;
        float v = bf[n];
#pragma unroll
        for (int e = 0; e < EMBD; e++)
            v += emb[c * EMBD + e] * Wf[(size_t)(IDIM + e) * IDIM + n];
        g_embW[i] = v;
    }
}

// ---------------- kernel 1: x = relu([h | emb] @ W_fuse + b)  (fp16 mma, ldmatrix) ----------------
// 256 threads (8 warps 2Mx4N), warp tile 64x32, BK=32, 4-stage ring, PAIRWISE slab compute.
__global__ __launch_bounds__(256, 2) void fuse_f16_kernel(const int* __restrict__ cids) {
    extern __shared__ uint8_t dsm[];
    __shared__ float sEmbW[NCLUST * 128];
    __shared__ int   scids[128];

    const int tid  = threadIdx.x;
    const int n0   = blockIdx.x * 128;
    const int m0   = blockIdx.y * 128;
    const int warp = tid >> 5, lane = tid & 31;
    const int gid  = lane >> 2, tig = lane & 3;
    const int wm   = (warp >> 2) * 64;        // 2 M-groups of 64
    const int wn   = (warp & 3) * 32;         // 4 N-groups of 32
    const uint32_t ub = smem_u32(dsm);

    // ldmatrix lane addressing
    const int a_row = lane & 15;
    const int a_k   = (lane >> 4) << 3;                 // 0 | 8
    const int b_row = (lane & 7) + ((lane >> 4) << 3);  // n-row within 16
    const int b_k   = ((lane >> 3) & 1) << 3;           // 0 | 8

    if (tid < 128) { int c = cids[m0 + tid]; scids[tid] = min(max(c, 0), CC); }
    for (int t = tid; t < NCLUST * 128; t += 256) {
        int c = t >> 7, j = t & 127;
        sEmbW[t] = g_embW[c * IDIM + n0 + j];
    }

    float acc[4][4][4];     // 4 M16-tiles x 4 N8-tiles
#pragma unroll
    for (int mi = 0; mi < 4; mi++)
#pragma unroll
        for (int ni = 0; ni < 4; ni++)
#pragma unroll
            for (int c = 0; c < 4; c++) acc[mi][ni][c] = 0.0f;

    auto load_slab = [&](int kt, int st) {
        const int k0 = kt * 32;
        const uint32_t sb = ub + st * STAGE_B;
#pragma unroll
        for (int i = 0; i < 2; i++) {                 // A: 128 rows x 4 chunks
            int idx = i * 256 + tid;
            int row = idx >> 2, ch = idx & 3;
            cp16(sb + row * ROW_B + ch * 16,
                 g_h16 + (size_t)(m0 + row) * IDIM + k0 + ch * 8);
        }
#pragma unroll
        for (int i = 0; i < 2; i++) {                 // B: 128 n-rows x 4 chunks
            int idx = i * 256 + tid;
            int row = idx >> 2, ch = idx & 3;
            cp16(sb + 10240 + row * ROW_B + ch * 16,
                 g_Wf16 + (size_t)(n0 + row) * IDIM + k0 + ch * 8);
        }
    };

    load_slab(0, 0); CP_COMMIT();
    load_slab(1, 1); CP_COMMIT();
    load_slab(2, 2); CP_COMMIT();
    load_slab(3, 3); CP_COMMIT();

    for (int p = 0; p < 8; p++) {
        if (p < 7) { CP_WAIT2(); } else { CP_WAIT0(); }
        __syncthreads();
#pragma unroll
        for (int q = 0; q < 2; q++) {
            const uint32_t sa = ub + ((2 * p + q) & 3) * STAGE_B;
            const uint32_t sb = sa + 10240;
#pragma unroll
            for (int ks = 0; ks < 2; ks++) {
                uint32_t af[4][4], bfr[4][2];
#pragma unroll
                for (int mi = 0; mi < 4; mi++)
                    ldsm_x4(af[mi], sa + (wm + mi * 16 + a_row) * ROW_B + (ks * 16 + a_k) * 2);
#pragma unroll
                for (int nj = 0; nj < 2; nj++)
                    ldsm_x4(&bfr[2 * nj][0], sb + (wn + nj * 16 + b_row) * ROW_B + (ks * 16 + b_k) * 2);
#pragma unroll
                for (int mi = 0; mi < 4; mi++)
#pragma unroll
                    for (int ni = 0; ni < 4; ni++)
                        mma_f16(acc[mi][ni], af[mi], bfr[ni]);
            }
        }
        __syncthreads();
        if (p < 6) {
            load_slab(2 * p + 4, (2 * p)     & 3); CP_COMMIT();
            load_slab(2 * p + 5, (2 * p + 1) & 3); CP_COMMIT();
        }
    }

    // epilogue: + embW(cid,n) (bias+emb folded), relu, store fp16
#pragma unroll
    for (int mi = 0; mi < 4; mi++) {
#pragma unroll
        for (int half = 0; half < 2; half++) {
            int ml = wm + mi * 16 + gid + half * 8;
            int m  = m0 + ml;
            const float* ew = &sEmbW[scids[ml] * 128];
#pragma unroll
            for (int ni = 0; ni < 4; ni++) {
                int nl = wn + ni * 8 + 2 * tig;
                float o0 = fmaxf(acc[mi][ni][half * 2 + 0] + ew[nl],     0.0f);
                float o1 = fmaxf(acc[mi][ni][half * 2 + 1] + ew[nl + 1], 0.0f);
                *(__half2*)&g_x16[(size_t)m * IDIM + n0 + nl] = __floats2half2_rn(o0, o1);
            }
        }
    }
}

// ---------------- kernel 2: intra gated attention logits (dual fp16 mma, ldmatrix) ----------------
// 256 threads (8 warps 2Mx4D), warp tile 64 rows x 16 d, PAIRWISE slab compute.
__global__ __launch_bounds__(256, 2) void attn1_f16_kernel(
    const float* __restrict__ ba1, const float* __restrict__ bb1,
    const float* __restrict__ Wc1) {
    extern __shared__ uint8_t dsm[];
    __shared__ float sba[64], sbb[64], swc[64];
    __shared__ float sA[128];

    const int tid  = threadIdx.x;
    const int d0   = blockIdx.x * 64;
    const int m0   = blockIdx.y * 128;
    const int warp = tid >> 5, lane = tid & 31;
    const int gid  = lane >> 2, tig = lane & 3;
    const int wm   = (warp >> 2) * 64;        // 2 M-groups of 64
    const int wn   = (warp & 3) * 16;         // 4 D-groups of 16
    const uint32_t ub = smem_u32(dsm);

    const int a_row = lane & 15;
    const int a_k   = (lane >> 4) << 3;
    const int b_row = (lane & 7) + ((lane >> 4) << 3);
    const int b_k   = ((lane >> 3) & 1) << 3;

    if (tid < 64) { sba[tid] = ba1[d0 + tid]; sbb[tid] = bb1[d0 + tid]; swc[tid] = Wc1[d0 + tid]; }
    if (tid < 128) sA[tid] = 0.0f;

    float acca[4][2][4], accg[4][2][4];
#pragma unroll
    for (int mi = 0; mi < 4; mi++)
#pragma unroll
        for (int ni = 0; ni < 2; ni++)
#pragma unroll
            for (int c = 0; c < 4; c++) { acca[mi][ni][c] = 0.0f; accg[mi][ni][c] = 0.0f; }

    auto load_slab = [&](int kt, int st) {
        const int k0 = kt * 32;
        const uint32_t sb = ub + st * STAGE_B;
#pragma unroll
        for (int i = 0; i < 2; i++) {                 // A (x): 128 rows x 4 chunks
            int idx = i * 256 + tid;
            int row = idx >> 2, ch = idx & 3;
            cp16(sb + row * ROW_B + ch * 16,
                 g_x16 + (size_t)(m0 + row) * IDIM + k0 + ch * 8);
        }
        // Ba (rows 0..63) then Bb (rows 64..127): 128 rows x 4 chunks = 512 items
#pragma unroll
        for (int i = 0; i < 2; i++) {
            int idx = i * 256 + tid;
            int row = idx >> 2, ch = idx & 3;       // row 0..127
            if (row < 64) {
                cp16(sb + 10240 + row * ROW_B + ch * 16,
                     g_Wa16 + (size_t)(d0 + row) * IDIM + k0 + ch * 8);
            } else {
                int r2 = row - 64;
                cp16(sb + 15360 + r2 * ROW_B + ch * 16,
                     g_Wb16 + (size_t)(d0 + r2) * IDIM + k0 + ch * 8);
            }
        }
    };

    load_slab(0, 0); CP_COMMIT();
    load_slab(1, 1); CP_COMMIT();
    load_slab(2, 2); CP_COMMIT();
    load_slab(3, 3); CP_COMMIT();

    for (int p = 0; p < 8; p++) {
        if (p < 7) { CP_WAIT2(); } else { CP_WAIT0(); }
        __syncthreads();
#pragma unroll
        for (int q = 0; q < 2; q++) {
            const uint32_t sax = ub + ((2 * p + q) & 3) * STAGE_B;
            const uint32_t sba_ = sax + 10240;
            const uint32_t sbb_ = sax + 15360;
#pragma unroll
            for (int ks = 0; ks < 2; ks++) {
                uint32_t af[4][4], ba_[2][2], bb_[2][2];
#pragma unroll
                for (int mi = 0; mi < 4; mi++)
                    ldsm_x4(af[mi], sax + (wm + mi * 16 + a_row) * ROW_B + (ks * 16 + a_k) * 2);
                ldsm_x4(&ba_[0][0], sba_ + (wn + b_row) * ROW_B + (ks * 16 + b_k) * 2);
                ldsm_x4(&bb_[0][0], sbb_ + (wn + b_row) * ROW_B + (ks * 16 + b_k) * 2);
#pragma unroll
                for (int mi = 0; mi < 4; mi++)
#pragma unroll
                    for (int ni = 0; ni < 2; ni++) {
                        mma_f16(acca[mi][ni], af[mi], ba_[ni]);
                        mma_f16(accg[mi][ni], af[mi], bb_[ni]);
                    }
            }
        }
        __syncthreads();
        if (p < 6) {
            load_slab(2 * p + 4, (2 * p)     & 3); CP_COMMIT();
            load_slab(2 * p + 5, (2 * p + 1) & 3); CP_COMMIT();
        }
    }

    // epilogue: gated pointwise + row reduction over this warp's 16-d slice
    float rsum[4][2];
#pragma unroll
    for (int mi = 0; mi < 4; mi++) { rsum[mi][0] = 0.0f; rsum[mi][1] = 0.0f; }
#pragma unroll
    for (int mi = 0; mi < 4; mi++)
#pragma unroll
        for (int ni = 0; ni < 2; ni++) {
            int nl = wn + ni * 8 + 2 * tig;
#pragma unroll
            for (int half = 0; half < 2; half++) {
#pragma unroll
                for (int col = 0; col < 2; col++) {
                    int dl = nl + col;
                    float va = tanhf(acca[mi][ni][half * 2 + col] + sba[dl]);
                    float vg = sigmoidf_(accg[mi][ni][half * 2 + col] + sbb[dl]);
                    rsum[mi][half] += va * vg * swc[dl];
                }
            }
        }
#pragma unroll
    for (int mi = 0; mi < 4; mi++)
#pragma unroll
        for (int half = 0; half < 2; half++) {
            float v = rsum[mi][half];
            v += __shfl_xor_sync(0xffffffffu, v, 1);
            v += __shfl_xor_sync(0xffffffffu, v, 2);
            if (tig == 0) atomicAdd(&sA[wm + mi * 16 + gid + half * 8], v);
        }
    __syncthreads();
    if (tid < 128) atomicAdd(&g_A[m0 + tid], sA[tid]);
}

// ---------------- kernel 3: segment max ----------------
__global__ void segmax_kernel(const int* __restrict__ cids) {
    __shared__ float smax[NSEG];
    const int tid = threadIdx.x;
    if (tid < NSEG) smax[tid] = -1e30f;
    __syncthreads();
    for (int m = blockIdx.x * blockDim.x + tid; m < MTOT; m += gridDim.x * blockDim.x) {
        int cid = cids[m];
        cid = min(max(cid, 0), CC);
        int seg = (m >> 14) * NCLUST + cid;
        atomicMaxFloat(&smax[seg], g_A[m]);
    }
    __syncthreads();
    if (tid < NSEG) atomicMaxFloat(&g_segmax[tid], smax[tid]);
}

// ---------------- kernel 4: ex = exp(A - segmax), segment sum + counts ----------------
__global__ void segsum_kernel(const int* __restrict__ cids) {
    __shared__ float ssum[NSEG];
    __shared__ int   scnt[NSEG];
    const int tid = threadIdx.x;
    if (tid < NSEG) { ssum[tid] = 0.0f; scnt[tid] = 0; }
    __syncthreads();
    for (int m = blockIdx.x * blockDim.x + tid; m < MTOT; m += gridDim.x * blockDim.x) {
        int cid = cids[m];
        cid = min(max(cid, 0), CC);
        int seg = (m >> 14) * NCLUST + cid;
        float ex = expf(g_A[m] - g_segmax[seg]);
        g_ex[m] = ex;
        atomicAdd(&ssum[seg], ex);
        atomicAdd(&scnt[seg], 1);
    }
    __syncthreads();
    if (tid < NSEG) {
        atomicAdd(&g_segsum[tid], ssum[tid]);
        atomicAdd(&g_counts[tid], scnt[tid]);
    }
}

// ---------------- kernel 5: cfraw[seg] += w * x[m]  (x in fp16, 128-row chunks) ----------------
__global__ __launch_bounds__(256) void cfeat_kernel(const int* __restrict__ cids) {
    __shared__ float sh[NCLUST][IDIM];
    const int tid = threadIdx.x;
    const int b     = blockIdx.x >> 7;    // 128 chunks per batch
    const int chunk = blockIdx.x & 127;
    for (int i = tid; i < NCLUST * IDIM; i += 256) ((float*)sh)[i] = 0.0f;
    __syncthreads();
    const int mbase = b * NPB + chunk * 128;
    for (int r = 0; r < 128; r++) {
        int m = mbase + r;
        int cid = cids[m];
        cid = min(max(cid, 0), CC);
        float w = g_ex[m] / g_segsum[b * NCLUST + cid];
        const __half* xr = &g_x16[(size_t)m * IDIM];
        sh[cid][tid]       += w * __half2float(xr[tid]);
        sh[cid][tid + 256] += w * __half2float(xr[tid + 256]);
    }
    __syncthreads();
    for (int c = 0; c < NCLUST; c++) {
        atomicAdd(&g_cfraw[(b * NCLUST + c) * IDIM + tid],       sh[c][tid]);
        atomicAdd(&g_cfraw[(b * NCLUST + c) * IDIM + tid + 256], sh[c][tid + 256]);
    }
}

// ---------------- kernel 6: cfeat = relu(cfraw @ W_intra + b_intra)  [88,512] ----------------
__global__ __launch_bounds__(256) void intra_kernel(
    const float* __restrict__ Wi, const float* __restrict__ bi)
{
    __shared__ float xr[IDIM];
    const int s = blockIdx.x, tid = threadIdx.x;
    xr[tid]       = g_cfraw[s * IDIM + tid];
    xr[tid + 256] = g_cfraw[s * IDIM + tid + 256];
    __syncthreads();
#pragma unroll
    for (int jj = 0; jj < 2; jj++) {
        int j = tid + jj * 256;
        float acc = bi[j];
        for (int k = 0; k < IDIM; k++) acc += xr[k] * Wi[(size_t)k * IDIM + j];
        g_cfeat[s * IDIM + j] = fmaxf(acc, 0.0f);
    }
}

// ---------------- kernel 7: inter-cluster gated logits A2[88] ----------------
__global__ __launch_bounds__(256) void attn2_kernel(
    const float* __restrict__ Wa2, const float* __restrict__ ba2,
    const float* __restrict__ Wb2, const float* __restrict__ bb2,
    const float* __restrict__ Wc2, const float* __restrict__ bc2)
{
    __shared__ float xr[IDIM];
    __shared__ float red[256];
    const int s = blockIdx.x, tid = threadIdx.x;
    xr[tid]       = g_cfeat[s * IDIM + tid];
    xr[tid + 256] = g_cfeat[s * IDIM + tid + 256];
    __syncthreads();
    float aa = ba2[tid], bb = bb2[tid];
    for (int k = 0; k < IDIM; k++) {
        float xv = xr[k];
        aa += xv * Wa2[(size_t)k * DDIM + tid];
        bb += xv * Wb2[(size_t)k * DDIM + tid];
    }
    red[tid] = tanhf(aa) * sigmoidf_(bb) * Wc2[tid];
    __syncthreads();
    for (int off = 128; off > 0; off >>= 1) {
        if (tid < off) red[tid] += red[tid + off];
        __syncthreads();
    }
    if (tid == 0)
        g_A2[s] = (g_counts[s] > 0) ? (red[0] + bc2[0]) : -1e30f;
}

// ---------------- kernel 8: per-batch softmax, pooling, classifier ----------------
__global__ __launch_bounds__(256) void final_kernel(
    const float* __restrict__ Wint, const float* __restrict__ bint,
    const float* __restrict__ Wcls, const float* __restrict__ bcls,
    float* __restrict__ out)
{
    __shared__ float sWs[NCLUST];
    __shared__ float sl[IDIM];
    __shared__ float st2[256];
    __shared__ float red[256];
    const int b = blockIdx.x, tid = threadIdx.x;

    if (tid == 0) {
        float mx = -1e30f;
        for (int c = 0; c < NCLUST; c++) mx = fmaxf(mx, g_A2[b * NCLUST + c]);
        float e[NCLUST]; float sum = 0.0f;
        for (int c = 0; c < NCLUST; c++) { e[c] = expf(g_A2[b * NCLUST + c] - mx); sum += e[c]; }
        for (int c = 0; c < NCLUST; c++) sWs[c] = e[c] / sum;
    }
    __syncthreads();

#pragma unroll
    for (int jj = 0; jj < 2; jj++) {
        int j = tid + jj * 256;
        float s = 0.0f;
        for (int c = 0; c < NCLUST; c++)
            s += sWs[c] * g_cfeat[(b * NCLUST + c) * IDIM + j];
        sl[j] = s;
    }
    __syncthreads();

    float acc = bint[tid];
    for (int k = 0; k < IDIM; k++) acc += sl[k] * Wint[(size_t)k * 256 + tid];
    st2[tid] = fmaxf(acc, 0.0f);
    __syncthreads();

    red[tid] = st2[tid] * Wcls[tid * 2 + 0];
    __syncthreads();
    for (int off = 128; off > 0; off >>= 1) {
        if (tid < off) red[tid] += red[tid + off];
        __syncthreads();
    }
    if (tid == 0) out[b * 2 + 0] = red[0] + bcls[0];
    __syncthreads();

    red[tid] = st2[tid] * Wcls[tid * 2 + 1];
    __syncthreads();
    for (int off = 128; off > 0; off >>= 1) {
        if (tid < off) red[tid] += red[tid + off];
        __syncthreads();
    }
    if (tid == 0) out[b * 2 + 1] = red[0] + bcls[1];
}

// ---------------- launch ----------------
extern "C" void kernel_launch(void* const* d_in, const int* in_sizes, int n_in,
                              void* d_out, int out_size)
{
    const float* h       = (const float*)d_in[0];
    const int*   cids    = (const int*)  d_in[1];
    const float* emb     = (const float*)d_in[2];
    const float* W_fuse  = (const float*)d_in[3];
    const float* b_fuse  = (const float*)d_in[4];
    const float* Wa1     = (const float*)d_in[5];
    const float* ba1     = (const float*)d_in[6];
    const float* Wb1     = (const float*)d_in[7];
    const float* bb1     = (const float*)d_in[8];
    const float* Wc1     = (const float*)d_in[9];
    // d_in[10] = bc1 (softmax-invariant, dropped)
    const float* W_intra = (const float*)d_in[11];
    const float* b_intra = (const float*)d_in[12];
    const float* Wa2     = (const float*)d_in[13];
    const float* ba2     = (const float*)d_in[14];
    const float* Wb2     = (const float*)d_in[15];
    const float* bb2     = (const float*)d_in[16];
    const float* Wc2     = (const float*)d_in[17];
    const float* bc2     = (const float*)d_in[18];
    const float* W_inter = (const float*)d_in[19];
    const float* b_inter = (const float*)d_in[20];
    const float* W_cls   = (const float*)d_in[21];
    const float* b_cls   = (const float*)d_in[22];
    float* out = (float*)d_out;

    // unconditional host attr sets (no static guards; capture-safe; idempotent)
    cudaFuncSetAttribute(fuse_f16_kernel,  cudaFuncAttributeMaxDynamicSharedMemorySize, GEMM_DSMEM);
    cudaFuncSetAttribute(attn1_f16_kernel, cudaFuncAttributeMaxDynamicSharedMemorySize, GEMM_DSMEM);

    init_kernel<<<256, 256>>>();
    prep_h_kernel<<<1024, 256>>>(h);
    prep_w_kernel<<<256, 256>>>(W_fuse, b_fuse, emb, Wa1, Wb1);
    fuse_f16_kernel<<<dim3(IDIM / 128, MTOT / 128), 256, GEMM_DSMEM>>>(cids);
    attn1_f16_kernel<<<dim3(DDIM / 64, MTOT / 128), 256, GEMM_DSMEM>>>(ba1, bb1, Wc1);
    segmax_kernel<<<256, 256>>>(cids);
    segsum_kernel<<<256, 256>>>(cids);
    cfeat_kernel<<<BATCH * 128, 256>>>(cids);
    intra_kernel<<<NSEG, 256>>>(W_intra, b_intra);
    attn2_kernel<<<NSEG, 256>>>(Wa2, ba2, Wb2, bb2, Wc2, bc2);
    final_kernel<<<BATCH, 256>>>(W_inter, b_inter, W_cls, b_cls, out);
}